// round 10
// baseline (speedup 1.0000x reference)
#include <cuda_runtime.h>
#include <cuda_bf16.h>
#include <cuda_fp16.h>
#include <math.h>
#include <stdint.h>

#define BB 4
#define SS 2048
#define HH 8
#define DD 64
#define NTOK (BB*SS*HH)   // 65536 tokens
#define LOG2E 1.4426950408889634f

// Scratch (allocation-free rule: __device__ globals)
__device__ __nv_bfloat16 g_qkh[(size_t)NTOK * 128];  // [n][128] q|k hi parts (q pre-scaled by log2e)
__device__ __nv_bfloat16 g_qkl[(size_t)NTOK * 128];  // [n][128] q|k lo parts
__device__ __half        g_v  [(size_t)NTOK * 64];   // [n][64]  v fp16
__device__ float         g_attn[(size_t)NTOK * 64];  // [n][64]  attention out
// Pre-transposed / split weights
__device__ __nv_bfloat16 g_wph[192 * 64];            // Wp^T [n][k] hi
__device__ __nv_bfloat16 g_wpl[192 * 64];            // Wp^T [n][k] lo
__device__ __nv_bfloat16 g_w1h[256 * 64];            // W1^T [n][k] hi
__device__ __nv_bfloat16 g_w1l[256 * 64];            // W1^T [n][k] lo
__device__ __half        g_w2h[64 * 256];            // W2^T [n][k] hi (fp16)
__device__ __half        g_w2l[64 * 256];            // W2^T [n][k] lo (fp16)

// ===========================================================================
// helpers
// ===========================================================================
__device__ __forceinline__ uint32_t smem_u32(const void* p) {
    uint32_t a;
    asm("{ .reg .u64 t; cvta.to.shared.u64 t, %1; cvt.u32.u64 %0, t; }"
        : "=r"(a) : "l"(p));
    return a;
}
__device__ __forceinline__ float ex2f(float x) {
    float y;
    asm("ex2.approx.ftz.f32 %0, %1;" : "=f"(y) : "f"(x));
    return y;
}
__device__ __forceinline__ uint32_t packh2(float a, float b) {
    __half2 h = __floats2half2_rn(a, b);
    return *reinterpret_cast<uint32_t*>(&h);
}
__device__ __forceinline__ uint32_t packbf2(float a, float b) {
    __nv_bfloat16 ha = __float2bfloat16(a), hb = __float2bfloat16(b);
    return (uint32_t)__bfloat16_as_ushort(ha) | ((uint32_t)__bfloat16_as_ushort(hb) << 16);
}
__device__ __forceinline__ void split2bf(float a, float b, uint32_t& hi, uint32_t& lo) {
    __nv_bfloat16 ha = __float2bfloat16(a), hb = __float2bfloat16(b);
    hi = (uint32_t)__bfloat16_as_ushort(ha) | ((uint32_t)__bfloat16_as_ushort(hb) << 16);
    lo = packbf2(a - __bfloat162float(ha), b - __bfloat162float(hb));
}
__device__ __forceinline__ float gelu_f(float z) {
    return 0.5f * z * (1.f + erff(z * 0.70710678118654752f));
}

#define LDSM_X4(r0,r1,r2,r3, addr) \
    asm volatile("ldmatrix.sync.aligned.m8n8.x4.shared.b16 {%0,%1,%2,%3}, [%4];" \
        : "=r"(r0), "=r"(r1), "=r"(r2), "=r"(r3) : "r"(addr))
#define LDSM_X4_T(r0,r1,r2,r3, addr) \
    asm volatile("ldmatrix.sync.aligned.m8n8.x4.trans.shared.b16 {%0,%1,%2,%3}, [%4];" \
        : "=r"(r0), "=r"(r1), "=r"(r2), "=r"(r3) : "r"(addr))

__device__ __forceinline__ void mma_bf(float* d, uint32_t a0, uint32_t a1,
                                       uint32_t a2, uint32_t a3,
                                       uint32_t b0, uint32_t b1) {
    asm volatile(
        "mma.sync.aligned.m16n8k16.row.col.f32.bf16.bf16.f32 "
        "{%0,%1,%2,%3}, {%4,%5,%6,%7}, {%8,%9}, {%0,%1,%2,%3};"
        : "+f"(d[0]), "+f"(d[1]), "+f"(d[2]), "+f"(d[3])
        : "r"(a0), "r"(a1), "r"(a2), "r"(a3), "r"(b0), "r"(b1));
}
__device__ __forceinline__ void mma_fp(float* d, uint32_t a0, uint32_t a1,
                                       uint32_t a2, uint32_t a3,
                                       uint32_t b0, uint32_t b1) {
    asm volatile(
        "mma.sync.aligned.m16n8k16.row.col.f32.f16.f16.f32 "
        "{%0,%1,%2,%3}, {%4,%5,%6,%7}, {%8,%9}, {%0,%1,%2,%3};"
        : "+f"(d[0]), "+f"(d[1]), "+f"(d[2]), "+f"(d[3])
        : "r"(a0), "r"(a1), "r"(a2), "r"(a3), "r"(b0), "r"(b1));
}

#define CPA(dst, src) asm volatile("cp.async.cg.shared.global [%0], [%1], 16;" \
        :: "r"(dst), "l"(src) : "memory")
#define CPC() asm volatile("cp.async.commit_group;" ::: "memory")
#define CPW(n) asm volatile("cp.async.wait_group %0;" :: "n"(n) : "memory")

// ===========================================================================
// Kernel 0: weight prep (transpose + split).  64 blocks x 256 threads.
// ===========================================================================
__global__ __launch_bounds__(256)
void kprep(const float* __restrict__ Wp, const float* __restrict__ W1,
           const float* __restrict__ W2)
{
    const int i = blockIdx.x * 256 + threadIdx.x;   // 0..16383
    if (i < 12288) {
        const int k = i / 192, n = i % 192;         // Wp [64][192]
        const float v = Wp[k * 192 + n];
        __nv_bfloat16 hv = __float2bfloat16(v);
        g_wph[n * 64 + k] = hv;
        g_wpl[n * 64 + k] = __float2bfloat16(v - __bfloat162float(hv));
    }
    {
        const int k = i >> 8, n = i & 255;          // W1 [64][256]
        const float v = W1[k * 256 + n];
        __nv_bfloat16 hv = __float2bfloat16(v);
        g_w1h[n * 64 + k] = hv;
        g_w1l[n * 64 + k] = __float2bfloat16(v - __bfloat162float(hv));
    }
    {
        const int k = i >> 6, n = i & 63;           // W2 [256][64]
        const float v = W2[k * 64 + n];
        __half hv = __float2half(v);
        g_w2h[n * 256 + k] = hv;
        g_w2l[n * 256 + k] = __float2half(v - __half2float(hv));
    }
}

// ===========================================================================
// Kernel 1: LN1 + QKV projection via HMMA (bf16 3-term).
// q columns pre-scaled by log2e before the hi/lo split (for exp2 softmax).
// ===========================================================================
#define K1_SW 17408
#define K1_TOTAL (K1_SW + 192 * 272)    // 69632

__global__ __launch_bounds__(256)
void k1_ln_qkv(const float* __restrict__ x,
               const float* __restrict__ g1, const float* __restrict__ b1v,
               const float* __restrict__ bp)
{
    extern __shared__ char smc[];
    const uint32_t sb = smem_u32(smc);
    const int tid = threadIdx.x;
    const int t0 = blockIdx.x * 64;

    for (int it = tid; it < 3072; it += 256) {
        const int n = it >> 4, c = it & 15;
        const char* src = (c < 8)
            ? (const char*)(g_wph + n * 64 + c * 8)
            : (const char*)(g_wpl + n * 64 + (c - 8) * 8);
        CPA(sb + K1_SW + n * 272 + c * 16, src);
    }
    CPC();

    {
        const int tt = tid >> 2, sub = tid & 3;
        const size_t base = ((size_t)(t0 + tt)) * 64 + sub * 16;
        float v[16];
        const float4* xp = (const float4*)(x + base);
        #pragma unroll
        for (int q = 0; q < 4; q++) {
            float4 f = xp[q];
            v[4*q+0] = f.x; v[4*q+1] = f.y; v[4*q+2] = f.z; v[4*q+3] = f.w;
        }
        float s = 0.f;
        #pragma unroll
        for (int q = 0; q < 16; q++) s += v[q];
        s += __shfl_xor_sync(0xffffffffu, s, 1);
        s += __shfl_xor_sync(0xffffffffu, s, 2);
        const float mean = s * (1.f / 64.f);
        float vs = 0.f;
        #pragma unroll
        for (int q = 0; q < 16; q++) { float d = v[q] - mean; vs += d * d; }
        vs += __shfl_xor_sync(0xffffffffu, vs, 1);
        vs += __shfl_xor_sync(0xffffffffu, vs, 2);
        const float rs = rsqrtf(vs * (1.f / 64.f) + 1e-5f);
        float r[16];
        #pragma unroll
        for (int q = 0; q < 16; q++) {
            const int d = sub * 16 + q;
            r[q] = (v[q] - mean) * rs * g1[d] + b1v[d];
        }
        uint32_t hw[8], lw[8];
        #pragma unroll
        for (int q = 0; q < 8; q++) split2bf(r[2*q], r[2*q+1], hw[q], lw[q]);
        char* dst = smc + (tt * 272 + sub * 32);
        *(uint4*)(dst)            = make_uint4(hw[0], hw[1], hw[2], hw[3]);
        *(uint4*)(dst + 16)       = make_uint4(hw[4], hw[5], hw[6], hw[7]);
        *(uint4*)(dst + 128)      = make_uint4(lw[0], lw[1], lw[2], lw[3]);
        *(uint4*)(dst + 128 + 16) = make_uint4(lw[4], lw[5], lw[6], lw[7]);
    }
    CPW(0);
    __syncthreads();

    const int wid = tid >> 5, lane = tid & 31;
    const int g = lane >> 3, lr = lane & 7;
    const int tg = (wid & 3) * 16;
    const int n0 = (wid >> 2) * 96;

    const uint32_t aA = sb + (uint32_t)(tg + (g & 1) * 8 + lr) * 272 + (g >> 1) * 16;
    const uint32_t bW = sb + K1_SW + (uint32_t)(n0 + (g >> 1) * 8 + lr) * 272 + (g & 1) * 16;

    float s[12][4];
    #pragma unroll
    for (int j = 0; j < 12; j++)
        #pragma unroll
        for (int e = 0; e < 4; e++) s[j][e] = 0.f;

    #pragma unroll
    for (int ks = 0; ks < 4; ks++) {
        uint32_t ah0, ah1, ah2, ah3, al0, al1, al2, al3;
        LDSM_X4(ah0, ah1, ah2, ah3, aA + ks * 32);
        LDSM_X4(al0, al1, al2, al3, aA + 128 + ks * 32);
        #pragma unroll
        for (int j = 0; j < 6; j++) {
            uint32_t wh0, wh1, wh2, wh3, wl0, wl1, wl2, wl3;
            LDSM_X4(wh0, wh1, wh2, wh3, bW + j * (16 * 272) + ks * 32);
            LDSM_X4(wl0, wl1, wl2, wl3, bW + j * (16 * 272) + 128 + ks * 32);
            mma_bf(s[2*j],     ah0, ah1, ah2, ah3, wh0, wh1);
            mma_bf(s[2*j + 1], ah0, ah1, ah2, ah3, wh2, wh3);
            mma_bf(s[2*j],     al0, al1, al2, al3, wh0, wh1);
            mma_bf(s[2*j + 1], al0, al1, al2, al3, wh2, wh3);
            mma_bf(s[2*j],     ah0, ah1, ah2, ah3, wl0, wl1);
            mma_bf(s[2*j + 1], ah0, ah1, ah2, ah3, wl2, wl3);
        }
    }

    const int r0 = t0 + tg + (lane >> 2);
    const int c0 = 2 * (lane & 3);
    #pragma unroll
    for (int idx = 0; idx < 12; idx++) {
        const int col = n0 + (idx >> 1) * 16 + (idx & 1) * 8 + c0;
        const float bb0 = bp[col], bb1 = bp[col + 1];
        float v0 = s[idx][0] + bb0, v1 = s[idx][1] + bb1;
        float v2 = s[idx][2] + bb0, v3 = s[idx][3] + bb1;
        if (col < 64) {   // q: pre-scale by log2e for exp2 softmax
            v0 *= LOG2E; v1 *= LOG2E; v2 *= LOG2E; v3 *= LOG2E;
        }
        if (col < 128) {
            uint32_t h01, l01, h23, l23;
            split2bf(v0, v1, h01, l01);
            split2bf(v2, v3, h23, l23);
            *(uint32_t*)(g_qkh + (size_t)r0 * 128 + col)       = h01;
            *(uint32_t*)(g_qkl + (size_t)r0 * 128 + col)       = l01;
            *(uint32_t*)(g_qkh + (size_t)(r0 + 8) * 128 + col) = h23;
            *(uint32_t*)(g_qkl + (size_t)(r0 + 8) * 128 + col) = l23;
        } else {
            *(uint32_t*)(g_v + (size_t)r0 * 64 + col - 128)       = packh2(v0, v1);
            *(uint32_t*)(g_v + (size_t)(r0 + 8) * 64 + col - 128) = packh2(v2, v3);
        }
    }
}

// smem byte layout for k2
#define QPITCH 272
#define KPITCH 272
#define VPITCH 144
#define SM_Q   0
#define SM_KB  (128 * QPITCH)               // 34816
#define KBUF   (64 * KPITCH)                // 17408
#define SM_VB  (SM_KB + 2 * KBUF)           // 69632
#define VBUF   (64 * VPITCH)                // 9216
#define SM2_TOTAL (SM_VB + 2 * VBUF)        // 88064

// ===========================================================================
// Kernel 2: flash attention.  QK: bf16 3-term hi/lo.  PV: fp16 1-term.
// Softmax in base-2 (Q pre-scaled by log2e).  Qh fragments held in registers.
// 256 threads (8 warps x 16 q-rows), 2 CTAs/SM.
// ===========================================================================
__global__ __launch_bounds__(256, 2)
void k2_attn_mma()
{
    extern __shared__ char smc[];
    const uint32_t sb = smem_u32(smc);

    const int tid  = threadIdx.x;
    const int wid  = tid >> 5;
    const int lane = tid & 31;
    const int b = blockIdx.y >> 3, h = blockIdx.y & 7;
    const int q0 = blockIdx.x * 128;
    const int m0 = wid * 16;

    const int g  = lane >> 3;
    const int lr = lane & 7;

    const uint32_t aQ   = sb + SM_Q + (uint32_t)(m0 + (g & 1) * 8 + lr) * QPITCH + (g >> 1) * 16;
    const uint32_t kOff = (uint32_t)((g >> 1) * 8 + lr) * KPITCH + (g & 1) * 16;
    const uint32_t vOff = (uint32_t)((g & 1) * 8 + lr) * VPITCH + (g >> 1) * 16;

    {
        for (int it = tid; it < 2048; it += 256) {
            const int row = it >> 4, c = it & 15;
            const size_t n = ((size_t)(b * SS + q0 + row)) * HH + h;
            const char* src = (c < 8)
                ? (const char*)(g_qkh + n * 128 + c * 8)
                : (const char*)(g_qkl + n * 128 + (c - 8) * 8);
            CPA(sb + SM_Q + row * QPITCH + c * 16, src);
        }
        for (int it = tid; it < 1024; it += 256) {
            const int row = it >> 4, c = it & 15;
            const size_t n = ((size_t)(b * SS + row)) * HH + h;
            const char* src = (c < 8)
                ? (const char*)(g_qkh + n * 128 + 64 + c * 8)
                : (const char*)(g_qkl + n * 128 + 64 + (c - 8) * 8);
            CPA(sb + SM_KB + row * KPITCH + c * 16, src);
        }
        for (int it = tid; it < 512; it += 256) {
            const int row = it >> 3, c = it & 7;
            const size_t n = ((size_t)(b * SS + row)) * HH + h;
            CPA(sb + SM_VB + row * VPITCH + c * 16, (const char*)(g_v + n * 64 + c * 8));
        }
        CPC();
    }

    // Qh fragments -> registers (loaded once, reused all 32 tiles)
    CPW(0);
    __syncthreads();
    uint32_t qh[4][4];
    #pragma unroll
    for (int ks = 0; ks < 4; ks++)
        LDSM_X4(qh[ks][0], qh[ks][1], qh[ks][2], qh[ks][3], aQ + ks * 32);

    float o[8][4];
    #pragma unroll
    for (int j = 0; j < 8; j++)
        #pragma unroll
        for (int e = 0; e < 4; e++) o[j][e] = 0.f;
    float mrow0 = -INFINITY, mrow1 = -INFINITY;
    float lsum0 = 0.f, lsum1 = 0.f;

    for (int kt = 0; kt < SS / 64; kt++) {
        __syncthreads();
        if (kt + 1 < SS / 64) {
            const int k0n = (kt + 1) * 64;
            const uint32_t dK = sb + SM_KB + ((kt + 1) & 1) * KBUF;
            const uint32_t dV = sb + SM_VB + ((kt + 1) & 1) * VBUF;
            for (int it = tid; it < 1024; it += 256) {
                const int row = it >> 4, c = it & 15;
                const size_t n = ((size_t)(b * SS + k0n + row)) * HH + h;
                const char* src = (c < 8)
                    ? (const char*)(g_qkh + n * 128 + 64 + c * 8)
                    : (const char*)(g_qkl + n * 128 + 64 + (c - 8) * 8);
                CPA(dK + row * KPITCH + c * 16, src);
            }
            for (int it = tid; it < 512; it += 256) {
                const int row = it >> 3, c = it & 7;
                const size_t n = ((size_t)(b * SS + k0n + row)) * HH + h;
                CPA(dV + row * VPITCH + c * 16, (const char*)(g_v + n * 64 + c * 8));
            }
            CPC();
            CPW(1);
        } else {
            CPW(0);
        }
        __syncthreads();

        const uint32_t bK = sb + SM_KB + (kt & 1) * KBUF + kOff;
        const uint32_t bV = sb + SM_VB + (kt & 1) * VBUF + vOff;

        // S = Qh*Kh + Ql*Kh + Qh*Kl  (logits already in base-2 domain)
        float s[8][4];
        #pragma unroll
        for (int j = 0; j < 8; j++)
            #pragma unroll
            for (int e = 0; e < 4; e++) s[j][e] = 0.f;

        #pragma unroll
        for (int ks = 0; ks < 4; ks++) {
            uint32_t ql0, ql1, ql2, ql3;
            LDSM_X4(ql0, ql1, ql2, ql3, aQ + 128 + ks * 32);
            #pragma unroll
            for (int j = 0; j < 4; j++) {
                uint32_t kh0, kh1, kh2, kh3, kl0, kl1, kl2, kl3;
                LDSM_X4(kh0, kh1, kh2, kh3, bK + j * (16 * KPITCH) + ks * 32);
                LDSM_X4(kl0, kl1, kl2, kl3, bK + j * (16 * KPITCH) + 128 + ks * 32);
                mma_bf(s[2*j],     qh[ks][0], qh[ks][1], qh[ks][2], qh[ks][3], kh0, kh1);
                mma_bf(s[2*j + 1], qh[ks][0], qh[ks][1], qh[ks][2], qh[ks][3], kh2, kh3);
                mma_bf(s[2*j],     ql0, ql1, ql2, ql3, kh0, kh1);
                mma_bf(s[2*j + 1], ql0, ql1, ql2, ql3, kh2, kh3);
                mma_bf(s[2*j],     qh[ks][0], qh[ks][1], qh[ks][2], qh[ks][3], kl0, kl1);
                mma_bf(s[2*j + 1], qh[ks][0], qh[ks][1], qh[ks][2], qh[ks][3], kl2, kl3);
            }
        }

        // online softmax (base-2)
        float t0 = -INFINITY, t1 = -INFINITY;
        #pragma unroll
        for (int j = 0; j < 8; j++) {
            t0 = fmaxf(t0, fmaxf(s[j][0], s[j][1]));
            t1 = fmaxf(t1, fmaxf(s[j][2], s[j][3]));
        }
        t0 = fmaxf(t0, __shfl_xor_sync(0xffffffffu, t0, 1));
        t0 = fmaxf(t0, __shfl_xor_sync(0xffffffffu, t0, 2));
        t1 = fmaxf(t1, __shfl_xor_sync(0xffffffffu, t1, 1));
        t1 = fmaxf(t1, __shfl_xor_sync(0xffffffffu, t1, 2));
        const float mn0 = fmaxf(mrow0, t0);
        const float mn1 = fmaxf(mrow1, t1);
        const float sc0 = ex2f(mrow0 - mn0);
        const float sc1 = ex2f(mrow1 - mn1);
        mrow0 = mn0; mrow1 = mn1;

        float acc0 = 0.f, acc1 = 0.f;
        #pragma unroll
        for (int j = 0; j < 8; j++) {
            s[j][0] = ex2f(s[j][0] - mn0);
            s[j][1] = ex2f(s[j][1] - mn0);
            s[j][2] = ex2f(s[j][2] - mn1);
            s[j][3] = ex2f(s[j][3] - mn1);
            acc0 += s[j][0] + s[j][1];
            acc1 += s[j][2] + s[j][3];
        }
        lsum0 = lsum0 * sc0 + acc0;
        lsum1 = lsum1 * sc1 + acc1;
        #pragma unroll
        for (int j = 0; j < 8; j++) {
            o[j][0] *= sc0; o[j][1] *= sc0;
            o[j][2] *= sc1; o[j][3] *= sc1;
        }

        // O += P * V (fp16 single-pass)
        #pragma unroll
        for (int kk = 0; kk < 4; kk++) {
            const uint32_t p0 = packh2(s[2*kk][0],     s[2*kk][1]);
            const uint32_t p1 = packh2(s[2*kk][2],     s[2*kk][3]);
            const uint32_t p2 = packh2(s[2*kk + 1][0], s[2*kk + 1][1]);
            const uint32_t p3 = packh2(s[2*kk + 1][2], s[2*kk + 1][3]);
            #pragma unroll
            for (int j = 0; j < 4; j++) {
                uint32_t v0, v1, v2, v3;
                LDSM_X4_T(v0, v1, v2, v3, bV + kk * (16 * VPITCH) + j * 32);
                mma_fp(o[2*j],     p0, p1, p2, p3, v0, v1);
                mma_fp(o[2*j + 1], p0, p1, p2, p3, v2, v3);
            }
        }
    }

    lsum0 += __shfl_xor_sync(0xffffffffu, lsum0, 1);
    lsum0 += __shfl_xor_sync(0xffffffffu, lsum0, 2);
    lsum1 += __shfl_xor_sync(0xffffffffu, lsum1, 1);
    lsum1 += __shfl_xor_sync(0xffffffffu, lsum1, 2);
    const float inv0 = 1.f / lsum0, inv1 = 1.f / lsum1;

    const int r0 = q0 + m0 + (lane >> 2);
    const int c0 = (lane & 3) * 2;
    const size_t n0 = ((size_t)(b * SS + r0)) * HH + h;
    const size_t n1 = ((size_t)(b * SS + r0 + 8)) * HH + h;
    #pragma unroll
    for (int j = 0; j < 8; j++) {
        float2 v0 = make_float2(o[j][0] * inv0, o[j][1] * inv0);
        float2 v1 = make_float2(o[j][2] * inv1, o[j][3] * inv1);
        *(float2*)(g_attn + n0 * 64 + 8 * j + c0) = v0;
        *(float2*)(g_attn + n1 * 64 + 8 * j + c0) = v1;
    }
}

// ===========================================================================
// Kernel 3 (fused): LN2 + GEMM1 + gelu + GEMM2 + K-split reduce + residual.
// (R9, unchanged)
// ===========================================================================
#define F3_A   0
#define F3_W1  34816
#define F3_W2  104448
#define F3_TOTAL 171008

__global__ __launch_bounds__(512, 1)
void k3_fused(const float* __restrict__ g2, const float* __restrict__ b2v,
              const float* __restrict__ b1m,
              const float* __restrict__ x, const float* __restrict__ b2m,
              float* __restrict__ out)
{
    extern __shared__ char smc[];
    const uint32_t sb = smem_u32(smc);
    const int tid = threadIdx.x;
    const int t0 = blockIdx.x * 128;

    for (int it = tid; it < 4096; it += 512) {
        const int n = it >> 4, c = it & 15;
        const char* src = (c < 8)
            ? (const char*)(g_w1h + n * 64 + c * 8)
            : (const char*)(g_w1l + n * 64 + (c - 8) * 8);
        CPA(sb + F3_W1 + n * 272 + c * 16, src);
    }
    for (int it = tid; it < 4096; it += 512) {
        const int n = it >> 6, c = it & 63;
        const char* src = (c < 32)
            ? (const char*)(g_w2h + n * 256 + c * 8)
            : (const char*)(g_w2l + n * 256 + (c - 32) * 8);
        CPA(sb + F3_W2 + n * 1040 + ((c < 32) ? c * 16 : 512 + (c - 32) * 16), src);
    }
    CPC();

    {
        const int tt = tid >> 2, sub = tid & 3;
        const size_t base = ((size_t)(t0 + tt)) * 64 + sub * 16;
        float v[16];
        const float4* ap = (const float4*)(g_attn + base);
        #pragma unroll
        for (int q = 0; q < 4; q++) {
            float4 f = ap[q];
            v[4*q+0] = f.x; v[4*q+1] = f.y; v[4*q+2] = f.z; v[4*q+3] = f.w;
        }
        float s = 0.f;
        #pragma unroll
        for (int q = 0; q < 16; q++) s += v[q];
        s += __shfl_xor_sync(0xffffffffu, s, 1);
        s += __shfl_xor_sync(0xffffffffu, s, 2);
        const float mean = s * (1.f / 64.f);
        float vs = 0.f;
        #pragma unroll
        for (int q = 0; q < 16; q++) { float d = v[q] - mean; vs += d * d; }
        vs += __shfl_xor_sync(0xffffffffu, vs, 1);
        vs += __shfl_xor_sync(0xffffffffu, vs, 2);
        const float rs = rsqrtf(vs * (1.f / 64.f) + 1e-5f);
        float r[16];
        #pragma unroll
        for (int q = 0; q < 16; q++) {
            const int d = sub * 16 + q;
            r[q] = (v[q] - mean) * rs * g2[d] + b2v[d];
        }
        uint32_t hw[8], lw[8];
        #pragma unroll
        for (int q = 0; q < 8; q++) split2bf(r[2*q], r[2*q+1], hw[q], lw[q]);
        char* dst = smc + F3_A + (tt * 272 + sub * 32);
        *(uint4*)(dst)            = make_uint4(hw[0], hw[1], hw[2], hw[3]);
        *(uint4*)(dst + 16)       = make_uint4(hw[4], hw[5], hw[6], hw[7]);
        *(uint4*)(dst + 128)      = make_uint4(lw[0], lw[1], lw[2], lw[3]);
        *(uint4*)(dst + 128 + 16) = make_uint4(lw[4], lw[5], lw[6], lw[7]);
    }
    CPW(0);
    __syncthreads();

    const int wid = tid >> 5, lane = tid & 31;
    const int g = lane >> 3, lr = lane & 7;
    const int tg = (wid & 7) * 16;
    const int n0 = (wid >> 3) * 128;

    const uint32_t aA = sb + F3_A + (uint32_t)(tg + (g & 1) * 8 + lr) * 272 + (g >> 1) * 16;
    const uint32_t bW1 = sb + F3_W1 + (uint32_t)(n0 + (g >> 1) * 8 + lr) * 272 + (g & 1) * 16;

    float s[16][4];
    #pragma unroll
    for (int j = 0; j < 16; j++)
        #pragma unroll
        for (int e = 0; e < 4; e++) s[j][e] = 0.f;

    #pragma unroll
    for (int ks = 0; ks < 4; ks++) {
        uint32_t ah0, ah1, ah2, ah3, al0, al1, al2, al3;
        LDSM_X4(ah0, ah1, ah2, ah3, aA + ks * 32);
        LDSM_X4(al0, al1, al2, al3, aA + 128 + ks * 32);
        #pragma unroll
        for (int j = 0; j < 8; j++) {
            uint32_t wh0, wh1, wh2, wh3, wl0, wl1, wl2, wl3;
            LDSM_X4(wh0, wh1, wh2, wh3, bW1 + j * (16 * 272) + ks * 32);
            LDSM_X4(wl0, wl1, wl2, wl3, bW1 + j * (16 * 272) + 128 + ks * 32);
            mma_bf(s[2*j],     ah0, ah1, ah2, ah3, wh0, wh1);
            mma_bf(s[2*j + 1], ah0, ah1, ah2, ah3, wh2, wh3);
            mma_bf(s[2*j],     al0, al1, al2, al3, wh0, wh1);
            mma_bf(s[2*j + 1], al0, al1, al2, al3, wh2, wh3);
            mma_bf(s[2*j],     ah0, ah1, ah2, ah3, wl0, wl1);
            mma_bf(s[2*j + 1], ah0, ah1, ah2, ah3, wl2, wl3);
        }
    }

    const int c0 = 2 * (lane & 3);
    uint32_t ph[8][4];
    #pragma unroll
    for (int gk = 0; gk < 8; gk++) {
        const int colA = n0 + gk * 16 + c0;
        const int colB = colA + 8;
        const float bA0 = b1m[colA], bA1 = b1m[colA + 1];
        const float bB0 = b1m[colB], bB1 = b1m[colB + 1];
        ph[gk][0] = packh2(gelu_f(s[2*gk][0] + bA0),     gelu_f(s[2*gk][1] + bA1));
        ph[gk][1] = packh2(gelu_f(s[2*gk][2] + bA0),     gelu_f(s[2*gk][3] + bA1));
        ph[gk][2] = packh2(gelu_f(s[2*gk + 1][0] + bB0), gelu_f(s[2*gk + 1][1] + bB1));
        ph[gk][3] = packh2(gelu_f(s[2*gk + 1][2] + bB0), gelu_f(s[2*gk + 1][3] + bB1));
    }

    const uint32_t bW2 = sb + F3_W2 + (uint32_t)((g >> 1) * 8 + lr) * 1040
                       + (g & 1) * 16 + (uint32_t)n0 * 2;
    float o[8][4];
    #pragma unroll
    for (int j = 0; j < 8; j++)
        #pragma unroll
        for (int e = 0; e < 4; e++) o[j][e] = 0.f;

    #pragma unroll
    for (int kk = 0; kk < 8; kk++) {
        const uint32_t p0 = ph[kk][0], p1 = ph[kk][1], p2 = ph[kk][2], p3 = ph[kk][3];
        #pragma unroll
        for (int j = 0; j < 4; j++) {
            uint32_t wh0, wh1, wh2, wh3, wl0, wl1, wl2, wl3;
            LDSM_X4(wh0, wh1, wh2, wh3, bW2 + j * (16 * 1040) + kk * 32);
            LDSM_X4(wl0, wl1, wl2, wl3, bW2 + j * (16 * 1040) + 512 + kk * 32);
            mma_fp(o[2*j],     p0, p1, p2, p3, wh0, wh1);
            mma_fp(o[2*j + 1], p0, p1, p2, p3, wh2, wh3);
            mma_fp(o[2*j],     p0, p1, p2, p3, wl0, wl1);
            mma_fp(o[2*j + 1], p0, p1, p2, p3, wl2, wl3);
        }
    }

    __syncthreads();

    float* red = (float*)(smc + F3_A);
    const int rowL0 = tg + (lane >> 2);
    if (wid >= 8) {
        #pragma unroll
        for (int idx = 0; idx < 8; idx++) {
            const int col = (idx >> 1) * 16 + (idx & 1) * 8 + c0;
            *(float2*)(red + rowL0 * 68 + col)       = make_float2(o[idx][0], o[idx][1]);
            *(float2*)(red + (rowL0 + 8) * 68 + col) = make_float2(o[idx][2], o[idx][3]);
        }
    }
    __syncthreads();

    if (wid < 8) {
        const int r0 = t0 + rowL0;
        #pragma unroll
        for (int idx = 0; idx < 8; idx++) {
            const int col = (idx >> 1) * 16 + (idx & 1) * 8 + c0;
            const float2 pa = *(const float2*)(red + rowL0 * 68 + col);
            const float2 pb = *(const float2*)(red + (rowL0 + 8) * 68 + col);
            const float bb0 = b2m[col], bb1 = b2m[col + 1];
            const size_t na = (size_t)r0 * 64 + col;
            const size_t nb = (size_t)(r0 + 8) * 64 + col;
            const float2 xa = *(const float2*)(x + na);
            const float2 xb = *(const float2*)(x + nb);
            *(float2*)(out + na) = make_float2(o[idx][0] + pa.x + bb0 + xa.x,
                                               o[idx][1] + pa.y + bb1 + xa.y);
            *(float2*)(out + nb) = make_float2(o[idx][2] + pb.x + bb0 + xb.x,
                                               o[idx][3] + pb.y + bb1 + xb.y);
        }
    }
}

// ===========================================================================
extern "C" void kernel_launch(void* const* d_in, const int* in_sizes, int n_in,
                              void* d_out, int out_size)
{
    const float* x    = (const float*)d_in[0];
    const float* ln1g = (const float*)d_in[1];
    const float* ln1b = (const float*)d_in[2];
    const float* Wp   = (const float*)d_in[3];
    const float* bp   = (const float*)d_in[4];
    const float* ln2g = (const float*)d_in[5];
    const float* ln2b = (const float*)d_in[6];
    const float* W1   = (const float*)d_in[7];
    const float* b1   = (const float*)d_in[8];
    const float* W2   = (const float*)d_in[9];
    const float* b2   = (const float*)d_in[10];
    float* out = (float*)d_out;

    cudaFuncSetAttribute(k1_ln_qkv,   cudaFuncAttributeMaxDynamicSharedMemorySize, K1_TOTAL);
    cudaFuncSetAttribute(k2_attn_mma, cudaFuncAttributeMaxDynamicSharedMemorySize, SM2_TOTAL);
    cudaFuncSetAttribute(k3_fused,    cudaFuncAttributeMaxDynamicSharedMemorySize, F3_TOTAL);

    kprep<<<64, 256>>>(Wp, W1, W2);
    k1_ln_qkv<<<NTOK / 64, 256, K1_TOTAL>>>(x, ln1g, ln1b, bp);
    k2_attn_mma<<<dim3(SS / 128, BB * HH), 256, SM2_TOTAL>>>();
    k3_fused<<<NTOK / 128, 512, F3_TOTAL>>>(ln2g, ln2b, b1, x, b2, out);
}

// round 11
// speedup vs baseline: 1.0210x; 1.0210x over previous
#include <cuda_runtime.h>
#include <cuda_bf16.h>
#include <cuda_fp16.h>
#include <math.h>
#include <stdint.h>

#define BB 4
#define SS 2048
#define HH 8
#define DD 64
#define NTOK (BB*SS*HH)   // 65536 tokens

// Scratch (allocation-free rule: __device__ globals)
__device__ __nv_bfloat16 g_qkh[(size_t)NTOK * 128];  // [n][128] q|k hi parts
__device__ __nv_bfloat16 g_qkl[(size_t)NTOK * 128];  // [n][128] q|k lo parts
__device__ __half        g_v  [(size_t)NTOK * 64];   // [n][64]  v fp16
__device__ float         g_attn[(size_t)NTOK * 64];  // [n][64]  attention out
// Pre-transposed / split weights
__device__ __nv_bfloat16 g_wph[192 * 64];            // Wp^T [n][k] hi
__device__ __nv_bfloat16 g_wpl[192 * 64];            // Wp^T [n][k] lo
__device__ __nv_bfloat16 g_w1h[256 * 64];            // W1^T [n][k] hi
__device__ __nv_bfloat16 g_w1l[256 * 64];            // W1^T [n][k] lo
__device__ __half        g_w2h[64 * 256];            // W2^T [n][k] hi (fp16)

// ===========================================================================
// helpers
// ===========================================================================
__device__ __forceinline__ uint32_t smem_u32(const void* p) {
    uint32_t a;
    asm("{ .reg .u64 t; cvta.to.shared.u64 t, %1; cvt.u32.u64 %0, t; }"
        : "=r"(a) : "l"(p));
    return a;
}
__device__ __forceinline__ uint32_t packh2(float a, float b) {
    __half2 h = __floats2half2_rn(a, b);
    return *reinterpret_cast<uint32_t*>(&h);
}
__device__ __forceinline__ uint32_t packbf2(float a, float b) {
    __nv_bfloat16 ha = __float2bfloat16(a), hb = __float2bfloat16(b);
    return (uint32_t)__bfloat16_as_ushort(ha) | ((uint32_t)__bfloat16_as_ushort(hb) << 16);
}
__device__ __forceinline__ void split2bf(float a, float b, uint32_t& hi, uint32_t& lo) {
    __nv_bfloat16 ha = __float2bfloat16(a), hb = __float2bfloat16(b);
    hi = (uint32_t)__bfloat16_as_ushort(ha) | ((uint32_t)__bfloat16_as_ushort(hb) << 16);
    lo = packbf2(a - __bfloat162float(ha), b - __bfloat162float(hb));
}
__device__ __forceinline__ float gelu_f(float z) {
    return 0.5f * z * (1.f + erff(z * 0.70710678118654752f));
}

#define LDSM_X4(r0,r1,r2,r3, addr) \
    asm volatile("ldmatrix.sync.aligned.m8n8.x4.shared.b16 {%0,%1,%2,%3}, [%4];" \
        : "=r"(r0), "=r"(r1), "=r"(r2), "=r"(r3) : "r"(addr))
#define LDSM_X4_T(r0,r1,r2,r3, addr) \
    asm volatile("ldmatrix.sync.aligned.m8n8.x4.trans.shared.b16 {%0,%1,%2,%3}, [%4];" \
        : "=r"(r0), "=r"(r1), "=r"(r2), "=r"(r3) : "r"(addr))

__device__ __forceinline__ void mma_bf(float* d, uint32_t a0, uint32_t a1,
                                       uint32_t a2, uint32_t a3,
                                       uint32_t b0, uint32_t b1) {
    asm volatile(
        "mma.sync.aligned.m16n8k16.row.col.f32.bf16.bf16.f32 "
        "{%0,%1,%2,%3}, {%4,%5,%6,%7}, {%8,%9}, {%0,%1,%2,%3};"
        : "+f"(d[0]), "+f"(d[1]), "+f"(d[2]), "+f"(d[3])
        : "r"(a0), "r"(a1), "r"(a2), "r"(a3), "r"(b0), "r"(b1));
}
__device__ __forceinline__ void mma_fp(float* d, uint32_t a0, uint32_t a1,
                                       uint32_t a2, uint32_t a3,
                                       uint32_t b0, uint32_t b1) {
    asm volatile(
        "mma.sync.aligned.m16n8k16.row.col.f32.f16.f16.f32 "
        "{%0,%1,%2,%3}, {%4,%5,%6,%7}, {%8,%9}, {%0,%1,%2,%3};"
        : "+f"(d[0]), "+f"(d[1]), "+f"(d[2]), "+f"(d[3])
        : "r"(a0), "r"(a1), "r"(a2), "r"(a3), "r"(b0), "r"(b1));
}

#define CPA(dst, src) asm volatile("cp.async.cg.shared.global [%0], [%1], 16;" \
        :: "r"(dst), "l"(src) : "memory")
#define CPC() asm volatile("cp.async.commit_group;" ::: "memory")
#define CPW(n) asm volatile("cp.async.wait_group %0;" :: "n"(n) : "memory")

// ===========================================================================
// Kernel 0: weight prep (transpose + split).  64 blocks x 256 threads.
// ===========================================================================
__global__ __launch_bounds__(256)
void kprep(const float* __restrict__ Wp, const float* __restrict__ W1,
           const float* __restrict__ W2)
{
    const int i = blockIdx.x * 256 + threadIdx.x;   // 0..16383
    if (i < 12288) {
        const int k = i / 192, n = i % 192;         // Wp [64][192]
        const float v = Wp[k * 192 + n];
        __nv_bfloat16 hv = __float2bfloat16(v);
        g_wph[n * 64 + k] = hv;
        g_wpl[n * 64 + k] = __float2bfloat16(v - __bfloat162float(hv));
    }
    {
        const int k = i >> 8, n = i & 255;          // W1 [64][256]
        const float v = W1[k * 256 + n];
        __nv_bfloat16 hv = __float2bfloat16(v);
        g_w1h[n * 64 + k] = hv;
        g_w1l[n * 64 + k] = __float2bfloat16(v - __bfloat162float(hv));
    }
    {
        const int k = i >> 6, n = i & 63;           // W2 [256][64]
        g_w2h[n * 256 + k] = __float2half(W2[k * 64 + n]);
    }
}

// ===========================================================================
// Kernel 1: LN1 + QKV projection via HMMA (bf16 3-term).  (R9, unchanged)
// ===========================================================================
#define K1_SW 17408
#define K1_TOTAL (K1_SW + 192 * 272)    // 69632

__global__ __launch_bounds__(256)
void k1_ln_qkv(const float* __restrict__ x,
               const float* __restrict__ g1, const float* __restrict__ b1v,
               const float* __restrict__ bp)
{
    extern __shared__ char smc[];
    const uint32_t sb = smem_u32(smc);
    const int tid = threadIdx.x;
    const int t0 = blockIdx.x * 64;

    for (int it = tid; it < 3072; it += 256) {
        const int n = it >> 4, c = it & 15;
        const char* src = (c < 8)
            ? (const char*)(g_wph + n * 64 + c * 8)
            : (const char*)(g_wpl + n * 64 + (c - 8) * 8);
        CPA(sb + K1_SW + n * 272 + c * 16, src);
    }
    CPC();

    {
        const int tt = tid >> 2, sub = tid & 3;
        const size_t base = ((size_t)(t0 + tt)) * 64 + sub * 16;
        float v[16];
        const float4* xp = (const float4*)(x + base);
        #pragma unroll
        for (int q = 0; q < 4; q++) {
            float4 f = xp[q];
            v[4*q+0] = f.x; v[4*q+1] = f.y; v[4*q+2] = f.z; v[4*q+3] = f.w;
        }
        float s = 0.f;
        #pragma unroll
        for (int q = 0; q < 16; q++) s += v[q];
        s += __shfl_xor_sync(0xffffffffu, s, 1);
        s += __shfl_xor_sync(0xffffffffu, s, 2);
        const float mean = s * (1.f / 64.f);
        float vs = 0.f;
        #pragma unroll
        for (int q = 0; q < 16; q++) { float d = v[q] - mean; vs += d * d; }
        vs += __shfl_xor_sync(0xffffffffu, vs, 1);
        vs += __shfl_xor_sync(0xffffffffu, vs, 2);
        const float rs = rsqrtf(vs * (1.f / 64.f) + 1e-5f);
        float r[16];
        #pragma unroll
        for (int q = 0; q < 16; q++) {
            const int d = sub * 16 + q;
            r[q] = (v[q] - mean) * rs * g1[d] + b1v[d];
        }
        uint32_t hw[8], lw[8];
        #pragma unroll
        for (int q = 0; q < 8; q++) split2bf(r[2*q], r[2*q+1], hw[q], lw[q]);
        char* dst = smc + (tt * 272 + sub * 32);
        *(uint4*)(dst)            = make_uint4(hw[0], hw[1], hw[2], hw[3]);
        *(uint4*)(dst + 16)       = make_uint4(hw[4], hw[5], hw[6], hw[7]);
        *(uint4*)(dst + 128)      = make_uint4(lw[0], lw[1], lw[2], lw[3]);
        *(uint4*)(dst + 128 + 16) = make_uint4(lw[4], lw[5], lw[6], lw[7]);
    }
    CPW(0);
    __syncthreads();

    const int wid = tid >> 5, lane = tid & 31;
    const int g = lane >> 3, lr = lane & 7;
    const int tg = (wid & 3) * 16;
    const int n0 = (wid >> 2) * 96;

    const uint32_t aA = sb + (uint32_t)(tg + (g & 1) * 8 + lr) * 272 + (g >> 1) * 16;
    const uint32_t bW = sb + K1_SW + (uint32_t)(n0 + (g >> 1) * 8 + lr) * 272 + (g & 1) * 16;

    float s[12][4];
    #pragma unroll
    for (int j = 0; j < 12; j++)
        #pragma unroll
        for (int e = 0; e < 4; e++) s[j][e] = 0.f;

    #pragma unroll
    for (int ks = 0; ks < 4; ks++) {
        uint32_t ah0, ah1, ah2, ah3, al0, al1, al2, al3;
        LDSM_X4(ah0, ah1, ah2, ah3, aA + ks * 32);
        LDSM_X4(al0, al1, al2, al3, aA + 128 + ks * 32);
        #pragma unroll
        for (int j = 0; j < 6; j++) {
            uint32_t wh0, wh1, wh2, wh3, wl0, wl1, wl2, wl3;
            LDSM_X4(wh0, wh1, wh2, wh3, bW + j * (16 * 272) + ks * 32);
            LDSM_X4(wl0, wl1, wl2, wl3, bW + j * (16 * 272) + 128 + ks * 32);
            mma_bf(s[2*j],     ah0, ah1, ah2, ah3, wh0, wh1);
            mma_bf(s[2*j + 1], ah0, ah1, ah2, ah3, wh2, wh3);
            mma_bf(s[2*j],     al0, al1, al2, al3, wh0, wh1);
            mma_bf(s[2*j + 1], al0, al1, al2, al3, wh2, wh3);
            mma_bf(s[2*j],     ah0, ah1, ah2, ah3, wl0, wl1);
            mma_bf(s[2*j + 1], ah0, ah1, ah2, ah3, wl2, wl3);
        }
    }

    const int r0 = t0 + tg + (lane >> 2);
    const int c0 = 2 * (lane & 3);
    #pragma unroll
    for (int idx = 0; idx < 12; idx++) {
        const int col = n0 + (idx >> 1) * 16 + (idx & 1) * 8 + c0;
        const float bb0 = bp[col], bb1 = bp[col + 1];
        const float v0 = s[idx][0] + bb0, v1 = s[idx][1] + bb1;
        const float v2 = s[idx][2] + bb0, v3 = s[idx][3] + bb1;
        if (col < 128) {
            uint32_t h01, l01, h23, l23;
            split2bf(v0, v1, h01, l01);
            split2bf(v2, v3, h23, l23);
            *(uint32_t*)(g_qkh + (size_t)r0 * 128 + col)       = h01;
            *(uint32_t*)(g_qkl + (size_t)r0 * 128 + col)       = l01;
            *(uint32_t*)(g_qkh + (size_t)(r0 + 8) * 128 + col) = h23;
            *(uint32_t*)(g_qkl + (size_t)(r0 + 8) * 128 + col) = l23;
        } else {
            *(uint32_t*)(g_v + (size_t)r0 * 64 + col - 128)       = packh2(v0, v1);
            *(uint32_t*)(g_v + (size_t)(r0 + 8) * 64 + col - 128) = packh2(v2, v3);
        }
    }
}

// smem byte layout for k2 (R9 shape, unchanged)
#define QPITCH 272
#define KPITCH 272
#define VPITCH 144
#define SM_Q   0
#define SM_KB  (128 * QPITCH)               // 34816
#define KBUF   (64 * KPITCH)                // 17408
#define SM_VB  (SM_KB + 2 * KBUF)           // 69632
#define VBUF   (64 * VPITCH)                // 9216
#define SM2_TOTAL (SM_VB + 2 * VBUF)        // 88064

// ===========================================================================
// Kernel 2: flash attention.  (R9, unchanged — known-good 293.3 build)
// ===========================================================================
__global__ __launch_bounds__(256, 2)
void k2_attn_mma()
{
    extern __shared__ char smc[];
    const uint32_t sb = smem_u32(smc);

    const int tid  = threadIdx.x;
    const int wid  = tid >> 5;
    const int lane = tid & 31;
    const int b = blockIdx.y >> 3, h = blockIdx.y & 7;
    const int q0 = blockIdx.x * 128;
    const int m0 = wid * 16;

    const int g  = lane >> 3;
    const int lr = lane & 7;

    const uint32_t aQ   = sb + SM_Q + (uint32_t)(m0 + (g & 1) * 8 + lr) * QPITCH + (g >> 1) * 16;
    const uint32_t kOff = (uint32_t)((g >> 1) * 8 + lr) * KPITCH + (g & 1) * 16;
    const uint32_t vOff = (uint32_t)((g & 1) * 8 + lr) * VPITCH + (g >> 1) * 16;

    {
        for (int it = tid; it < 2048; it += 256) {
            const int row = it >> 4, c = it & 15;
            const size_t n = ((size_t)(b * SS + q0 + row)) * HH + h;
            const char* src = (c < 8)
                ? (const char*)(g_qkh + n * 128 + c * 8)
                : (const char*)(g_qkl + n * 128 + (c - 8) * 8);
            CPA(sb + SM_Q + row * QPITCH + c * 16, src);
        }
        for (int it = tid; it < 1024; it += 256) {
            const int row = it >> 4, c = it & 15;
            const size_t n = ((size_t)(b * SS + row)) * HH + h;
            const char* src = (c < 8)
                ? (const char*)(g_qkh + n * 128 + 64 + c * 8)
                : (const char*)(g_qkl + n * 128 + 64 + (c - 8) * 8);
            CPA(sb + SM_KB + row * KPITCH + c * 16, src);
        }
        for (int it = tid; it < 512; it += 256) {
            const int row = it >> 3, c = it & 7;
            const size_t n = ((size_t)(b * SS + row)) * HH + h;
            CPA(sb + SM_VB + row * VPITCH + c * 16, (const char*)(g_v + n * 64 + c * 8));
        }
        CPC();
    }

    float o[8][4];
    #pragma unroll
    for (int j = 0; j < 8; j++)
        #pragma unroll
        for (int e = 0; e < 4; e++) o[j][e] = 0.f;
    float mrow0 = -INFINITY, mrow1 = -INFINITY;
    float lsum0 = 0.f, lsum1 = 0.f;

    for (int kt = 0; kt < SS / 64; kt++) {
        __syncthreads();
        if (kt + 1 < SS / 64) {
            const int k0n = (kt + 1) * 64;
            const uint32_t dK = sb + SM_KB + ((kt + 1) & 1) * KBUF;
            const uint32_t dV = sb + SM_VB + ((kt + 1) & 1) * VBUF;
            for (int it = tid; it < 1024; it += 256) {
                const int row = it >> 4, c = it & 15;
                const size_t n = ((size_t)(b * SS + k0n + row)) * HH + h;
                const char* src = (c < 8)
                    ? (const char*)(g_qkh + n * 128 + 64 + c * 8)
                    : (const char*)(g_qkl + n * 128 + 64 + (c - 8) * 8);
                CPA(dK + row * KPITCH + c * 16, src);
            }
            for (int it = tid; it < 512; it += 256) {
                const int row = it >> 3, c = it & 7;
                const size_t n = ((size_t)(b * SS + k0n + row)) * HH + h;
                CPA(dV + row * VPITCH + c * 16, (const char*)(g_v + n * 64 + c * 8));
            }
            CPC();
            CPW(1);
        } else {
            CPW(0);
        }
        __syncthreads();

        const uint32_t bK = sb + SM_KB + (kt & 1) * KBUF + kOff;
        const uint32_t bV = sb + SM_VB + (kt & 1) * VBUF + vOff;

        float s[8][4];
        #pragma unroll
        for (int j = 0; j < 8; j++)
            #pragma unroll
            for (int e = 0; e < 4; e++) s[j][e] = 0.f;

        #pragma unroll
        for (int ks = 0; ks < 4; ks++) {
            uint32_t qh0, qh1, qh2, qh3, ql0, ql1, ql2, ql3;
            LDSM_X4(qh0, qh1, qh2, qh3, aQ + ks * 32);
            LDSM_X4(ql0, ql1, ql2, ql3, aQ + 128 + ks * 32);
            #pragma unroll
            for (int j = 0; j < 4; j++) {
                uint32_t kh0, kh1, kh2, kh3, kl0, kl1, kl2, kl3;
                LDSM_X4(kh0, kh1, kh2, kh3, bK + j * (16 * KPITCH) + ks * 32);
                LDSM_X4(kl0, kl1, kl2, kl3, bK + j * (16 * KPITCH) + 128 + ks * 32);
                mma_bf(s[2*j],     qh0, qh1, qh2, qh3, kh0, kh1);
                mma_bf(s[2*j + 1], qh0, qh1, qh2, qh3, kh2, kh3);
                mma_bf(s[2*j],     ql0, ql1, ql2, ql3, kh0, kh1);
                mma_bf(s[2*j + 1], ql0, ql1, ql2, ql3, kh2, kh3);
                mma_bf(s[2*j],     qh0, qh1, qh2, qh3, kl0, kl1);
                mma_bf(s[2*j + 1], qh0, qh1, qh2, qh3, kl2, kl3);
            }
        }

        float t0 = -INFINITY, t1 = -INFINITY;
        #pragma unroll
        for (int j = 0; j < 8; j++) {
            t0 = fmaxf(t0, fmaxf(s[j][0], s[j][1]));
            t1 = fmaxf(t1, fmaxf(s[j][2], s[j][3]));
        }
        t0 = fmaxf(t0, __shfl_xor_sync(0xffffffffu, t0, 1));
        t0 = fmaxf(t0, __shfl_xor_sync(0xffffffffu, t0, 2));
        t1 = fmaxf(t1, __shfl_xor_sync(0xffffffffu, t1, 1));
        t1 = fmaxf(t1, __shfl_xor_sync(0xffffffffu, t1, 2));
        const float mn0 = fmaxf(mrow0, t0);
        const float mn1 = fmaxf(mrow1, t1);
        const float sc0 = __expf(mrow0 - mn0);
        const float sc1 = __expf(mrow1 - mn1);
        mrow0 = mn0; mrow1 = mn1;

        float acc0 = 0.f, acc1 = 0.f;
        #pragma unroll
        for (int j = 0; j < 8; j++) {
            s[j][0] = __expf(s[j][0] - mn0);
            s[j][1] = __expf(s[j][1] - mn0);
            s[j][2] = __expf(s[j][2] - mn1);
            s[j][3] = __expf(s[j][3] - mn1);
            acc0 += s[j][0] + s[j][1];
            acc1 += s[j][2] + s[j][3];
        }
        lsum0 = lsum0 * sc0 + acc0;
        lsum1 = lsum1 * sc1 + acc1;
        #pragma unroll
        for (int j = 0; j < 8; j++) {
            o[j][0] *= sc0; o[j][1] *= sc0;
            o[j][2] *= sc1; o[j][3] *= sc1;
        }

        #pragma unroll
        for (int kk = 0; kk < 4; kk++) {
            const uint32_t p0 = packh2(s[2*kk][0],     s[2*kk][1]);
            const uint32_t p1 = packh2(s[2*kk][2],     s[2*kk][3]);
            const uint32_t p2 = packh2(s[2*kk + 1][0], s[2*kk + 1][1]);
            const uint32_t p3 = packh2(s[2*kk + 1][2], s[2*kk + 1][3]);
            #pragma unroll
            for (int j = 0; j < 4; j++) {
                uint32_t v0, v1, v2, v3;
                LDSM_X4_T(v0, v1, v2, v3, bV + kk * (16 * VPITCH) + j * 32);
                mma_fp(o[2*j],     p0, p1, p2, p3, v0, v1);
                mma_fp(o[2*j + 1], p0, p1, p2, p3, v2, v3);
            }
        }
    }

    lsum0 += __shfl_xor_sync(0xffffffffu, lsum0, 1);
    lsum0 += __shfl_xor_sync(0xffffffffu, lsum0, 2);
    lsum1 += __shfl_xor_sync(0xffffffffu, lsum1, 1);
    lsum1 += __shfl_xor_sync(0xffffffffu, lsum1, 2);
    const float inv0 = 1.f / lsum0, inv1 = 1.f / lsum1;

    const int r0 = q0 + m0 + (lane >> 2);
    const int c0 = (lane & 3) * 2;
    const size_t n0 = ((size_t)(b * SS + r0)) * HH + h;
    const size_t n1 = ((size_t)(b * SS + r0 + 8)) * HH + h;
    #pragma unroll
    for (int j = 0; j < 8; j++) {
        float2 v0 = make_float2(o[j][0] * inv0, o[j][1] * inv0);
        float2 v1 = make_float2(o[j][2] * inv1, o[j][3] * inv1);
        *(float2*)(g_attn + n0 * 64 + 8 * j + c0) = v0;
        *(float2*)(g_attn + n1 * 64 + 8 * j + c0) = v1;
    }
}

// ===========================================================================
// Kernel 3 (fused, 32-token, 2 CTA/SM): LN2 + GEMM1 (bf16 3-term) + gelu
// + GEMM2 (fp16 SINGLE-term, 4-way K-split) + reduce via dead W1 region
// + bias + residual -> out.
// 256 threads (8 warps): warp w -> tokens (w&1)*16.., cols/k-range (w>>1)*64.
// smem: A @0 (8704) ; W1T @8704 (69632, reused as reduce bufs) ; W2h @78336 (33792).
// Total 112128 -> 2 CTAs/SM.  grid = NTOK/32 = 2048.
// ===========================================================================
#define F3_A   0
#define F3_W1  8704
#define F3_W2  78336
#define F3_TOTAL 112128

__global__ __launch_bounds__(256, 2)
void k3_fused(const float* __restrict__ g2, const float* __restrict__ b2v,
              const float* __restrict__ b1m,
              const float* __restrict__ x, const float* __restrict__ b2m,
              float* __restrict__ out)
{
    extern __shared__ char smc[];
    const uint32_t sb = smem_u32(smc);
    const int tid = threadIdx.x;
    const int t0 = blockIdx.x * 32;

    // async-load W1T hi/lo: 256 rows x 16 chunks
    for (int it = tid; it < 4096; it += 256) {
        const int n = it >> 4, c = it & 15;
        const char* src = (c < 8)
            ? (const char*)(g_w1h + n * 64 + c * 8)
            : (const char*)(g_w1l + n * 64 + (c - 8) * 8);
        CPA(sb + F3_W1 + n * 272 + c * 16, src);
    }
    // async-load W2h fp16: 64 rows x 32 chunks (512B data, pitch 528)
    for (int it = tid; it < 2048; it += 256) {
        const int n = it >> 5, c = it & 31;
        CPA(sb + F3_W2 + n * 528 + c * 16, (const char*)(g_w2h + n * 256 + c * 8));
    }
    CPC();

    // LN2: 8 threads/token, 8 elems each; split hi/lo into A tile
    {
        const int tt = tid >> 3, sub = tid & 7;
        const size_t base = ((size_t)(t0 + tt)) * 64 + sub * 8;
        const float4* ap = (const float4*)(g_attn + base);
        float4 f0 = ap[0], f1 = ap[1];
        float v[8] = { f0.x, f0.y, f0.z, f0.w, f1.x, f1.y, f1.z, f1.w };
        float s = 0.f;
        #pragma unroll
        for (int q = 0; q < 8; q++) s += v[q];
        s += __shfl_xor_sync(0xffffffffu, s, 1);
        s += __shfl_xor_sync(0xffffffffu, s, 2);
        s += __shfl_xor_sync(0xffffffffu, s, 4);
        const float mean = s * (1.f / 64.f);
        float vs = 0.f;
        #pragma unroll
        for (int q = 0; q < 8; q++) { float d = v[q] - mean; vs += d * d; }
        vs += __shfl_xor_sync(0xffffffffu, vs, 1);
        vs += __shfl_xor_sync(0xffffffffu, vs, 2);
        vs += __shfl_xor_sync(0xffffffffu, vs, 4);
        const float rs = rsqrtf(vs * (1.f / 64.f) + 1e-5f);
        float r[8];
        #pragma unroll
        for (int q = 0; q < 8; q++) {
            const int d = sub * 8 + q;
            r[q] = (v[q] - mean) * rs * g2[d] + b2v[d];
        }
        uint32_t hw[4], lw[4];
        #pragma unroll
        for (int q = 0; q < 4; q++) split2bf(r[2*q], r[2*q+1], hw[q], lw[q]);
        char* dst = smc + F3_A + (tt * 272 + sub * 16);
        *(uint4*)(dst)       = make_uint4(hw[0], hw[1], hw[2], hw[3]);
        *(uint4*)(dst + 128) = make_uint4(lw[0], lw[1], lw[2], lw[3]);
    }
    CPW(0);
    __syncthreads();

    const int wid = tid >> 5, lane = tid & 31;
    const int g = lane >> 3, lr = lane & 7;
    const int tg = (wid & 1) * 16;     // token group
    const int cg = wid >> 1;           // col group 0..3 (64 h1-cols, also GEMM2 k-range)
    const int n0 = cg * 64;

    const uint32_t aA  = sb + F3_A  + (uint32_t)(tg + (g & 1) * 8 + lr) * 272 + (g >> 1) * 16;
    const uint32_t bW1 = sb + F3_W1 + (uint32_t)(n0 + (g >> 1) * 8 + lr) * 272 + (g & 1) * 16;

    // ---- GEMM1: s[8][4] = LN2(attn) @ W1[:, n0:n0+64] (3-term bf16) ----
    float s[8][4];
    #pragma unroll
    for (int j = 0; j < 8; j++)
        #pragma unroll
        for (int e = 0; e < 4; e++) s[j][e] = 0.f;

    #pragma unroll
    for (int ks = 0; ks < 4; ks++) {
        uint32_t ah0, ah1, ah2, ah3, al0, al1, al2, al3;
        LDSM_X4(ah0, ah1, ah2, ah3, aA + ks * 32);
        LDSM_X4(al0, al1, al2, al3, aA + 128 + ks * 32);
        #pragma unroll
        for (int j = 0; j < 4; j++) {
            uint32_t wh0, wh1, wh2, wh3, wl0, wl1, wl2, wl3;
            LDSM_X4(wh0, wh1, wh2, wh3, bW1 + j * (16 * 272) + ks * 32);
            LDSM_X4(wl0, wl1, wl2, wl3, bW1 + j * (16 * 272) + 128 + ks * 32);
            mma_bf(s[2*j],     ah0, ah1, ah2, ah3, wh0, wh1);
            mma_bf(s[2*j + 1], ah0, ah1, ah2, ah3, wh2, wh3);
            mma_bf(s[2*j],     al0, al1, al2, al3, wh0, wh1);
            mma_bf(s[2*j + 1], al0, al1, al2, al3, wh2, wh3);
            mma_bf(s[2*j],     ah0, ah1, ah2, ah3, wl0, wl1);
            mma_bf(s[2*j + 1], ah0, ah1, ah2, ah3, wl2, wl3);
        }
    }

    // ---- gelu + pack H fragments in registers (A-fragment layout) ----
    const int c0 = 2 * (lane & 3);
    uint32_t ph[4][4];
    #pragma unroll
    for (int gk = 0; gk < 4; gk++) {
        const int colA = n0 + gk * 16 + c0;
        const int colB = colA + 8;
        const float bA0 = b1m[colA], bA1 = b1m[colA + 1];
        const float bB0 = b1m[colB], bB1 = b1m[colB + 1];
        ph[gk][0] = packh2(gelu_f(s[2*gk][0] + bA0),     gelu_f(s[2*gk][1] + bA1));
        ph[gk][1] = packh2(gelu_f(s[2*gk][2] + bA0),     gelu_f(s[2*gk][3] + bA1));
        ph[gk][2] = packh2(gelu_f(s[2*gk + 1][0] + bB0), gelu_f(s[2*gk + 1][1] + bB1));
        ph[gk][3] = packh2(gelu_f(s[2*gk + 1][2] + bB0), gelu_f(s[2*gk + 1][3] + bB1));
    }

    // ---- GEMM2: o = H @ W2 partial over k in [n0, n0+64) (fp16 single) ----
    const uint32_t bW2 = sb + F3_W2 + (uint32_t)((g >> 1) * 8 + lr) * 528
                       + (g & 1) * 16 + (uint32_t)n0 * 2;
    float o[8][4];
    #pragma unroll
    for (int j = 0; j < 8; j++)
        #pragma unroll
        for (int e = 0; e < 4; e++) o[j][e] = 0.f;

    #pragma unroll
    for (int kk = 0; kk < 4; kk++) {
        const uint32_t p0 = ph[kk][0], p1 = ph[kk][1], p2 = ph[kk][2], p3 = ph[kk][3];
        #pragma unroll
        for (int j = 0; j < 4; j++) {
            uint32_t w0, w1, w2, w3;
            LDSM_X4(w0, w1, w2, w3, bW2 + j * (16 * 528) + kk * 32);
            mma_fp(o[2*j],     p0, p1, p2, p3, w0, w1);
            mma_fp(o[2*j + 1], p0, p1, p2, p3, w2, w3);
        }
    }

    // ---- 4-way K-split reduce via dead W1 region ----
    __syncthreads();   // all W1/A reads complete

    const int rowL = tg + (lane >> 2);
    if (cg > 0) {
        float* rb = (float*)(smc + F3_W1 + (uint32_t)(cg - 1) * 8704);  // [32][68]
        #pragma unroll
        for (int idx = 0; idx < 8; idx++) {
            const int col = (idx >> 1) * 16 + (idx & 1) * 8 + c0;
            *(float2*)(rb + rowL * 68 + col)       = make_float2(o[idx][0], o[idx][1]);
            *(float2*)(rb + (rowL + 8) * 68 + col) = make_float2(o[idx][2], o[idx][3]);
        }
    }
    __syncthreads();

    if (cg == 0) {
        const float* rb0 = (const float*)(smc + F3_W1);
        const float* rb1 = (const float*)(smc + F3_W1 + 8704);
        const float* rb2 = (const float*)(smc + F3_W1 + 17408);
        const int r0 = t0 + rowL;
        #pragma unroll
        for (int idx = 0; idx < 8; idx++) {
            const int col = (idx >> 1) * 16 + (idx & 1) * 8 + c0;
            const int oa = rowL * 68 + col, ob = (rowL + 8) * 68 + col;
            const float2 a0 = *(const float2*)(rb0 + oa), b0f = *(const float2*)(rb0 + ob);
            const float2 a1 = *(const float2*)(rb1 + oa), b1f = *(const float2*)(rb1 + ob);
            const float2 a2 = *(const float2*)(rb2 + oa), b2f = *(const float2*)(rb2 + ob);
            const float bb0 = b2m[col], bb1 = b2m[col + 1];
            const size_t na = (size_t)r0 * 64 + col;
            const size_t nb = (size_t)(r0 + 8) * 64 + col;
            const float2 xa = *(const float2*)(x + na);
            const float2 xb = *(const float2*)(x + nb);
            *(float2*)(out + na) = make_float2(
                o[idx][0] + a0.x + a1.x + a2.x + bb0 + xa.x,
                o[idx][1] + a0.y + a1.y + a2.y + bb1 + xa.y);
            *(float2*)(out + nb) = make_float2(
                o[idx][2] + b0f.x + b1f.x + b2f.x + bb0 + xb.x,
                o[idx][3] + b0f.y + b1f.y + b2f.y + bb1 + xb.y);
        }
    }
}

// ===========================================================================
extern "C" void kernel_launch(void* const* d_in, const int* in_sizes, int n_in,
                              void* d_out, int out_size)
{
    const float* x    = (const float*)d_in[0];
    const float* ln1g = (const float*)d_in[1];
    const float* ln1b = (const float*)d_in[2];
    const float* Wp   = (const float*)d_in[3];
    const float* bp   = (const float*)d_in[4];
    const float* ln2g = (const float*)d_in[5];
    const float* ln2b = (const float*)d_in[6];
    const float* W1   = (const float*)d_in[7];
    const float* b1   = (const float*)d_in[8];
    const float* W2   = (const float*)d_in[9];
    const float* b2   = (const float*)d_in[10];
    float* out = (float*)d_out;

    cudaFuncSetAttribute(k1_ln_qkv,   cudaFuncAttributeMaxDynamicSharedMemorySize, K1_TOTAL);
    cudaFuncSetAttribute(k2_attn_mma, cudaFuncAttributeMaxDynamicSharedMemorySize, SM2_TOTAL);
    cudaFuncSetAttribute(k3_fused,    cudaFuncAttributeMaxDynamicSharedMemorySize, F3_TOTAL);

    kprep<<<64, 256>>>(Wp, W1, W2);
    k1_ln_qkv<<<NTOK / 64, 256, K1_TOTAL>>>(x, ln1g, ln1b, bp);
    k2_attn_mma<<<dim3(SS / 128, BB * HH), 256, SM2_TOTAL>>>();
    k3_fused<<<NTOK / 32, 256, F3_TOTAL>>>(ln2g, ln2b, b1, x, b2, out);
}

// round 12
// speedup vs baseline: 1.0639x; 1.0420x over previous
#include <cuda_runtime.h>
#include <cuda_bf16.h>
#include <cuda_fp16.h>
#include <math.h>
#include <stdint.h>

#define BB 4
#define SS 2048
#define HH 8
#define DD 64
#define NTOK (BB*SS*HH)   // 65536 tokens

// Scratch (allocation-free rule: __device__ globals)
__device__ __nv_bfloat16 g_qkh[(size_t)NTOK * 128];  // [n][128] q|k hi parts
__device__ __nv_bfloat16 g_qkl[(size_t)NTOK * 128];  // [n][128] q|k lo parts
__device__ __half        g_v  [(size_t)NTOK * 64];   // [n][64]  v fp16
__device__ float         g_attn[(size_t)NTOK * 64];  // [n][64]  attention out
// Pre-transposed / split weights
__device__ __nv_bfloat16 g_wph[192 * 64];            // Wp^T [n][k] hi (bf16)
__device__ __nv_bfloat16 g_wpl[192 * 64];            // Wp^T [n][k] lo (bf16)
__device__ __half        g_w1h[256 * 64];            // W1^T [n][k] hi (fp16)
__device__ __half        g_w1l[256 * 64];            // W1^T [n][k] lo (fp16)
__device__ __half        g_w2h[64 * 256];            // W2^T [n][k] (fp16)

// ===========================================================================
// helpers
// ===========================================================================
__device__ __forceinline__ uint32_t smem_u32(const void* p) {
    uint32_t a;
    asm("{ .reg .u64 t; cvta.to.shared.u64 t, %1; cvt.u32.u64 %0, t; }"
        : "=r"(a) : "l"(p));
    return a;
}
__device__ __forceinline__ uint32_t packh2(float a, float b) {
    __half2 h = __floats2half2_rn(a, b);
    return *reinterpret_cast<uint32_t*>(&h);
}
__device__ __forceinline__ uint32_t packbf2(float a, float b) {
    __nv_bfloat16 ha = __float2bfloat16(a), hb = __float2bfloat16(b);
    return (uint32_t)__bfloat16_as_ushort(ha) | ((uint32_t)__bfloat16_as_ushort(hb) << 16);
}
__device__ __forceinline__ void split2bf(float a, float b, uint32_t& hi, uint32_t& lo) {
    __nv_bfloat16 ha = __float2bfloat16(a), hb = __float2bfloat16(b);
    hi = (uint32_t)__bfloat16_as_ushort(ha) | ((uint32_t)__bfloat16_as_ushort(hb) << 16);
    lo = packbf2(a - __bfloat162float(ha), b - __bfloat162float(hb));
}
__device__ __forceinline__ float gelu_f(float z) {
    return 0.5f * z * (1.f + erff(z * 0.70710678118654752f));
}

#define LDSM_X4(r0,r1,r2,r3, addr) \
    asm volatile("ldmatrix.sync.aligned.m8n8.x4.shared.b16 {%0,%1,%2,%3}, [%4];" \
        : "=r"(r0), "=r"(r1), "=r"(r2), "=r"(r3) : "r"(addr))
#define LDSM_X4_T(r0,r1,r2,r3, addr) \
    asm volatile("ldmatrix.sync.aligned.m8n8.x4.trans.shared.b16 {%0,%1,%2,%3}, [%4];" \
        : "=r"(r0), "=r"(r1), "=r"(r2), "=r"(r3) : "r"(addr))

__device__ __forceinline__ void mma_bf(float* d, uint32_t a0, uint32_t a1,
                                       uint32_t a2, uint32_t a3,
                                       uint32_t b0, uint32_t b1) {
    asm volatile(
        "mma.sync.aligned.m16n8k16.row.col.f32.bf16.bf16.f32 "
        "{%0,%1,%2,%3}, {%4,%5,%6,%7}, {%8,%9}, {%0,%1,%2,%3};"
        : "+f"(d[0]), "+f"(d[1]), "+f"(d[2]), "+f"(d[3])
        : "r"(a0), "r"(a1), "r"(a2), "r"(a3), "r"(b0), "r"(b1));
}
__device__ __forceinline__ void mma_fp(float* d, uint32_t a0, uint32_t a1,
                                       uint32_t a2, uint32_t a3,
                                       uint32_t b0, uint32_t b1) {
    asm volatile(
        "mma.sync.aligned.m16n8k16.row.col.f32.f16.f16.f32 "
        "{%0,%1,%2,%3}, {%4,%5,%6,%7}, {%8,%9}, {%0,%1,%2,%3};"
        : "+f"(d[0]), "+f"(d[1]), "+f"(d[2]), "+f"(d[3])
        : "r"(a0), "r"(a1), "r"(a2), "r"(a3), "r"(b0), "r"(b1));
}

#define CPA(dst, src) asm volatile("cp.async.cg.shared.global [%0], [%1], 16;" \
        :: "r"(dst), "l"(src) : "memory")
#define CPC() asm volatile("cp.async.commit_group;" ::: "memory")
#define CPW(n) asm volatile("cp.async.wait_group %0;" :: "n"(n) : "memory")

// ===========================================================================
// Kernel 0: weight prep (transpose + split).  64 blocks x 256 threads.
// ===========================================================================
__global__ __launch_bounds__(256)
void kprep(const float* __restrict__ Wp, const float* __restrict__ W1,
           const float* __restrict__ W2)
{
    const int i = blockIdx.x * 256 + threadIdx.x;   // 0..16383
    if (i < 12288) {
        const int k = i / 192, n = i % 192;         // Wp [64][192]
        const float v = Wp[k * 192 + n];
        __nv_bfloat16 hv = __float2bfloat16(v);
        g_wph[n * 64 + k] = hv;
        g_wpl[n * 64 + k] = __float2bfloat16(v - __bfloat162float(hv));
    }
    {
        const int k = i >> 8, n = i & 255;          // W1 [64][256] -> fp16 hi/lo
        const float v = W1[k * 256 + n];
        __half hv = __float2half(v);
        g_w1h[n * 64 + k] = hv;
        g_w1l[n * 64 + k] = __float2half(v - __half2float(hv));
    }
    {
        const int k = i >> 6, n = i & 63;           // W2 [256][64]
        g_w2h[n * 256 + k] = __float2half(W2[k * 64 + n]);
    }
}

// ===========================================================================
// Kernel 1: LN1 + QKV projection via HMMA (bf16 3-term).  (unchanged)
// ===========================================================================
#define K1_SW 17408
#define K1_TOTAL (K1_SW + 192 * 272)    // 69632

__global__ __launch_bounds__(256)
void k1_ln_qkv(const float* __restrict__ x,
               const float* __restrict__ g1, const float* __restrict__ b1v,
               const float* __restrict__ bp)
{
    extern __shared__ char smc[];
    const uint32_t sb = smem_u32(smc);
    const int tid = threadIdx.x;
    const int t0 = blockIdx.x * 64;

    for (int it = tid; it < 3072; it += 256) {
        const int n = it >> 4, c = it & 15;
        const char* src = (c < 8)
            ? (const char*)(g_wph + n * 64 + c * 8)
            : (const char*)(g_wpl + n * 64 + (c - 8) * 8);
        CPA(sb + K1_SW + n * 272 + c * 16, src);
    }
    CPC();

    {
        const int tt = tid >> 2, sub = tid & 3;
        const size_t base = ((size_t)(t0 + tt)) * 64 + sub * 16;
        float v[16];
        const float4* xp = (const float4*)(x + base);
        #pragma unroll
        for (int q = 0; q < 4; q++) {
            float4 f = xp[q];
            v[4*q+0] = f.x; v[4*q+1] = f.y; v[4*q+2] = f.z; v[4*q+3] = f.w;
        }
        float s = 0.f;
        #pragma unroll
        for (int q = 0; q < 16; q++) s += v[q];
        s += __shfl_xor_sync(0xffffffffu, s, 1);
        s += __shfl_xor_sync(0xffffffffu, s, 2);
        const float mean = s * (1.f / 64.f);
        float vs = 0.f;
        #pragma unroll
        for (int q = 0; q < 16; q++) { float d = v[q] - mean; vs += d * d; }
        vs += __shfl_xor_sync(0xffffffffu, vs, 1);
        vs += __shfl_xor_sync(0xffffffffu, vs, 2);
        const float rs = rsqrtf(vs * (1.f / 64.f) + 1e-5f);
        float r[16];
        #pragma unroll
        for (int q = 0; q < 16; q++) {
            const int d = sub * 16 + q;
            r[q] = (v[q] - mean) * rs * g1[d] + b1v[d];
        }
        uint32_t hw[8], lw[8];
        #pragma unroll
        for (int q = 0; q < 8; q++) split2bf(r[2*q], r[2*q+1], hw[q], lw[q]);
        char* dst = smc + (tt * 272 + sub * 32);
        *(uint4*)(dst)            = make_uint4(hw[0], hw[1], hw[2], hw[3]);
        *(uint4*)(dst + 16)       = make_uint4(hw[4], hw[5], hw[6], hw[7]);
        *(uint4*)(dst + 128)      = make_uint4(lw[0], lw[1], lw[2], lw[3]);
        *(uint4*)(dst + 128 + 16) = make_uint4(lw[4], lw[5], lw[6], lw[7]);
    }
    CPW(0);
    __syncthreads();

    const int wid = tid >> 5, lane = tid & 31;
    const int g = lane >> 3, lr = lane & 7;
    const int tg = (wid & 3) * 16;
    const int n0 = (wid >> 2) * 96;

    const uint32_t aA = sb + (uint32_t)(tg + (g & 1) * 8 + lr) * 272 + (g >> 1) * 16;
    const uint32_t bW = sb + K1_SW + (uint32_t)(n0 + (g >> 1) * 8 + lr) * 272 + (g & 1) * 16;

    float s[12][4];
    #pragma unroll
    for (int j = 0; j < 12; j++)
        #pragma unroll
        for (int e = 0; e < 4; e++) s[j][e] = 0.f;

    #pragma unroll
    for (int ks = 0; ks < 4; ks++) {
        uint32_t ah0, ah1, ah2, ah3, al0, al1, al2, al3;
        LDSM_X4(ah0, ah1, ah2, ah3, aA + ks * 32);
        LDSM_X4(al0, al1, al2, al3, aA + 128 + ks * 32);
        #pragma unroll
        for (int j = 0; j < 6; j++) {
            uint32_t wh0, wh1, wh2, wh3, wl0, wl1, wl2, wl3;
            LDSM_X4(wh0, wh1, wh2, wh3, bW + j * (16 * 272) + ks * 32);
            LDSM_X4(wl0, wl1, wl2, wl3, bW + j * (16 * 272) + 128 + ks * 32);
            mma_bf(s[2*j],     ah0, ah1, ah2, ah3, wh0, wh1);
            mma_bf(s[2*j + 1], ah0, ah1, ah2, ah3, wh2, wh3);
            mma_bf(s[2*j],     al0, al1, al2, al3, wh0, wh1);
            mma_bf(s[2*j + 1], al0, al1, al2, al3, wh2, wh3);
            mma_bf(s[2*j],     ah0, ah1, ah2, ah3, wl0, wl1);
            mma_bf(s[2*j + 1], ah0, ah1, ah2, ah3, wl2, wl3);
        }
    }

    const int r0 = t0 + tg + (lane >> 2);
    const int c0 = 2 * (lane & 3);
    #pragma unroll
    for (int idx = 0; idx < 12; idx++) {
        const int col = n0 + (idx >> 1) * 16 + (idx & 1) * 8 + c0;
        const float bb0 = bp[col], bb1 = bp[col + 1];
        const float v0 = s[idx][0] + bb0, v1 = s[idx][1] + bb1;
        const float v2 = s[idx][2] + bb0, v3 = s[idx][3] + bb1;
        if (col < 128) {
            uint32_t h01, l01, h23, l23;
            split2bf(v0, v1, h01, l01);
            split2bf(v2, v3, h23, l23);
            *(uint32_t*)(g_qkh + (size_t)r0 * 128 + col)       = h01;
            *(uint32_t*)(g_qkl + (size_t)r0 * 128 + col)       = l01;
            *(uint32_t*)(g_qkh + (size_t)(r0 + 8) * 128 + col) = h23;
            *(uint32_t*)(g_qkl + (size_t)(r0 + 8) * 128 + col) = l23;
        } else {
            *(uint32_t*)(g_v + (size_t)r0 * 64 + col - 128)       = packh2(v0, v1);
            *(uint32_t*)(g_v + (size_t)(r0 + 8) * 64 + col - 128) = packh2(v2, v3);
        }
    }
}

// smem byte layout for k2 (unchanged)
#define QPITCH 272
#define KPITCH 272
#define VPITCH 144
#define SM_Q   0
#define SM_KB  (128 * QPITCH)               // 34816
#define KBUF   (64 * KPITCH)                // 17408
#define SM_VB  (SM_KB + 2 * KBUF)           // 69632
#define VBUF   (64 * VPITCH)                // 9216
#define SM2_TOTAL (SM_VB + 2 * VBUF)        // 88064

// ===========================================================================
// Kernel 2: flash attention.  (unchanged — known-good)
// ===========================================================================
__global__ __launch_bounds__(256, 2)
void k2_attn_mma()
{
    extern __shared__ char smc[];
    const uint32_t sb = smem_u32(smc);

    const int tid  = threadIdx.x;
    const int wid  = tid >> 5;
    const int lane = tid & 31;
    const int b = blockIdx.y >> 3, h = blockIdx.y & 7;
    const int q0 = blockIdx.x * 128;
    const int m0 = wid * 16;

    const int g  = lane >> 3;
    const int lr = lane & 7;

    const uint32_t aQ   = sb + SM_Q + (uint32_t)(m0 + (g & 1) * 8 + lr) * QPITCH + (g >> 1) * 16;
    const uint32_t kOff = (uint32_t)((g >> 1) * 8 + lr) * KPITCH + (g & 1) * 16;
    const uint32_t vOff = (uint32_t)((g & 1) * 8 + lr) * VPITCH + (g >> 1) * 16;

    {
        for (int it = tid; it < 2048; it += 256) {
            const int row = it >> 4, c = it & 15;
            const size_t n = ((size_t)(b * SS + q0 + row)) * HH + h;
            const char* src = (c < 8)
                ? (const char*)(g_qkh + n * 128 + c * 8)
                : (const char*)(g_qkl + n * 128 + (c - 8) * 8);
            CPA(sb + SM_Q + row * QPITCH + c * 16, src);
        }
        for (int it = tid; it < 1024; it += 256) {
            const int row = it >> 4, c = it & 15;
            const size_t n = ((size_t)(b * SS + row)) * HH + h;
            const char* src = (c < 8)
                ? (const char*)(g_qkh + n * 128 + 64 + c * 8)
                : (const char*)(g_qkl + n * 128 + 64 + (c - 8) * 8);
            CPA(sb + SM_KB + row * KPITCH + c * 16, src);
        }
        for (int it = tid; it < 512; it += 256) {
            const int row = it >> 3, c = it & 7;
            const size_t n = ((size_t)(b * SS + row)) * HH + h;
            CPA(sb + SM_VB + row * VPITCH + c * 16, (const char*)(g_v + n * 64 + c * 8));
        }
        CPC();
    }

    float o[8][4];
    #pragma unroll
    for (int j = 0; j < 8; j++)
        #pragma unroll
        for (int e = 0; e < 4; e++) o[j][e] = 0.f;
    float mrow0 = -INFINITY, mrow1 = -INFINITY;
    float lsum0 = 0.f, lsum1 = 0.f;

    for (int kt = 0; kt < SS / 64; kt++) {
        __syncthreads();
        if (kt + 1 < SS / 64) {
            const int k0n = (kt + 1) * 64;
            const uint32_t dK = sb + SM_KB + ((kt + 1) & 1) * KBUF;
            const uint32_t dV = sb + SM_VB + ((kt + 1) & 1) * VBUF;
            for (int it = tid; it < 1024; it += 256) {
                const int row = it >> 4, c = it & 15;
                const size_t n = ((size_t)(b * SS + k0n + row)) * HH + h;
                const char* src = (c < 8)
                    ? (const char*)(g_qkh + n * 128 + 64 + c * 8)
                    : (const char*)(g_qkl + n * 128 + 64 + (c - 8) * 8);
                CPA(dK + row * KPITCH + c * 16, src);
            }
            for (int it = tid; it < 512; it += 256) {
                const int row = it >> 3, c = it & 7;
                const size_t n = ((size_t)(b * SS + k0n + row)) * HH + h;
                CPA(dV + row * VPITCH + c * 16, (const char*)(g_v + n * 64 + c * 8));
            }
            CPC();
            CPW(1);
        } else {
            CPW(0);
        }
        __syncthreads();

        const uint32_t bK = sb + SM_KB + (kt & 1) * KBUF + kOff;
        const uint32_t bV = sb + SM_VB + (kt & 1) * VBUF + vOff;

        float s[8][4];
        #pragma unroll
        for (int j = 0; j < 8; j++)
            #pragma unroll
            for (int e = 0; e < 4; e++) s[j][e] = 0.f;

        #pragma unroll
        for (int ks = 0; ks < 4; ks++) {
            uint32_t qh0, qh1, qh2, qh3, ql0, ql1, ql2, ql3;
            LDSM_X4(qh0, qh1, qh2, qh3, aQ + ks * 32);
            LDSM_X4(ql0, ql1, ql2, ql3, aQ + 128 + ks * 32);
            #pragma unroll
            for (int j = 0; j < 4; j++) {
                uint32_t kh0, kh1, kh2, kh3, kl0, kl1, kl2, kl3;
                LDSM_X4(kh0, kh1, kh2, kh3, bK + j * (16 * KPITCH) + ks * 32);
                LDSM_X4(kl0, kl1, kl2, kl3, bK + j * (16 * KPITCH) + 128 + ks * 32);
                mma_bf(s[2*j],     qh0, qh1, qh2, qh3, kh0, kh1);
                mma_bf(s[2*j + 1], qh0, qh1, qh2, qh3, kh2, kh3);
                mma_bf(s[2*j],     ql0, ql1, ql2, ql3, kh0, kh1);
                mma_bf(s[2*j + 1], ql0, ql1, ql2, ql3, kh2, kh3);
                mma_bf(s[2*j],     qh0, qh1, qh2, qh3, kl0, kl1);
                mma_bf(s[2*j + 1], qh0, qh1, qh2, qh3, kl2, kl3);
            }
        }

        float t0 = -INFINITY, t1 = -INFINITY;
        #pragma unroll
        for (int j = 0; j < 8; j++) {
            t0 = fmaxf(t0, fmaxf(s[j][0], s[j][1]));
            t1 = fmaxf(t1, fmaxf(s[j][2], s[j][3]));
        }
        t0 = fmaxf(t0, __shfl_xor_sync(0xffffffffu, t0, 1));
        t0 = fmaxf(t0, __shfl_xor_sync(0xffffffffu, t0, 2));
        t1 = fmaxf(t1, __shfl_xor_sync(0xffffffffu, t1, 1));
        t1 = fmaxf(t1, __shfl_xor_sync(0xffffffffu, t1, 2));
        const float mn0 = fmaxf(mrow0, t0);
        const float mn1 = fmaxf(mrow1, t1);
        const float sc0 = __expf(mrow0 - mn0);
        const float sc1 = __expf(mrow1 - mn1);
        mrow0 = mn0; mrow1 = mn1;

        float acc0 = 0.f, acc1 = 0.f;
        #pragma unroll
        for (int j = 0; j < 8; j++) {
            s[j][0] = __expf(s[j][0] - mn0);
            s[j][1] = __expf(s[j][1] - mn0);
            s[j][2] = __expf(s[j][2] - mn1);
            s[j][3] = __expf(s[j][3] - mn1);
            acc0 += s[j][0] + s[j][1];
            acc1 += s[j][2] + s[j][3];
        }
        lsum0 = lsum0 * sc0 + acc0;
        lsum1 = lsum1 * sc1 + acc1;
        #pragma unroll
        for (int j = 0; j < 8; j++) {
            o[j][0] *= sc0; o[j][1] *= sc0;
            o[j][2] *= sc1; o[j][3] *= sc1;
        }

        #pragma unroll
        for (int kk = 0; kk < 4; kk++) {
            const uint32_t p0 = packh2(s[2*kk][0],     s[2*kk][1]);
            const uint32_t p1 = packh2(s[2*kk][2],     s[2*kk][3]);
            const uint32_t p2 = packh2(s[2*kk + 1][0], s[2*kk + 1][1]);
            const uint32_t p3 = packh2(s[2*kk + 1][2], s[2*kk + 1][3]);
            #pragma unroll
            for (int j = 0; j < 4; j++) {
                uint32_t v0, v1, v2, v3;
                LDSM_X4_T(v0, v1, v2, v3, bV + kk * (16 * VPITCH) + j * 32);
                mma_fp(o[2*j],     p0, p1, p2, p3, v0, v1);
                mma_fp(o[2*j + 1], p0, p1, p2, p3, v2, v3);
            }
        }
    }

    lsum0 += __shfl_xor_sync(0xffffffffu, lsum0, 1);
    lsum0 += __shfl_xor_sync(0xffffffffu, lsum0, 2);
    lsum1 += __shfl_xor_sync(0xffffffffu, lsum1, 1);
    lsum1 += __shfl_xor_sync(0xffffffffu, lsum1, 2);
    const float inv0 = 1.f / lsum0, inv1 = 1.f / lsum1;

    const int r0 = q0 + m0 + (lane >> 2);
    const int c0 = (lane & 3) * 2;
    const size_t n0 = ((size_t)(b * SS + r0)) * HH + h;
    const size_t n1 = ((size_t)(b * SS + r0 + 8)) * HH + h;
    #pragma unroll
    for (int j = 0; j < 8; j++) {
        float2 v0 = make_float2(o[j][0] * inv0, o[j][1] * inv0);
        float2 v1 = make_float2(o[j][2] * inv1, o[j][3] * inv1);
        *(float2*)(g_attn + n0 * 64 + 8 * j + c0) = v0;
        *(float2*)(g_attn + n1 * 64 + 8 * j + c0) = v1;
    }
}

// ===========================================================================
// Kernel 3 (fused v2): LN2 + GEMM1 (A fp16 single x W1 fp16 2-term) + gelu
// + GEMM2 (fp16 single, 2-way K-split) + reduce via dead W1 region
// + bias + residual -> out.
// 64 tokens/block, 256 threads (8 warps), 2 CTAs/SM.  grid = NTOK/64 = 1024.
// warp w: tokens (w&3)*16.., col/k-range (w>>2)*128.
// smem: A @0 (9216, fp16, pitch 144) ; W1 @9216 (69632, pitch 272, hi|lo) ;
//       W2h @78848 (33792, pitch 528).  Total 112640.
// ===========================================================================
#define F3_A   0
#define F3_W1  9216
#define F3_W2  78848
#define F3_TOTAL 112640

__global__ __launch_bounds__(256, 2)
void k3_fused(const float* __restrict__ g2, const float* __restrict__ b2v,
              const float* __restrict__ b1m,
              const float* __restrict__ x, const float* __restrict__ b2m,
              float* __restrict__ out)
{
    extern __shared__ char smc[];
    const uint32_t sb = smem_u32(smc);
    const int tid = threadIdx.x;
    const int t0 = blockIdx.x * 64;

    // async-load W1 hi/lo fp16: 256 rows x 16 chunks, pitch 272 ([hi 128B|lo 128B])
    for (int it = tid; it < 4096; it += 256) {
        const int n = it >> 4, c = it & 15;
        const char* src = (c < 8)
            ? (const char*)(g_w1h + n * 64 + c * 8)
            : (const char*)(g_w1l + n * 64 + (c - 8) * 8);
        CPA(sb + F3_W1 + n * 272 + c * 16, src);
    }
    // async-load W2h fp16: 64 rows x 32 chunks, pitch 528
    for (int it = tid; it < 2048; it += 256) {
        const int n = it >> 5, c = it & 31;
        CPA(sb + F3_W2 + n * 528 + c * 16, (const char*)(g_w2h + n * 256 + c * 8));
    }
    CPC();

    // LN2: 4 threads/token, 16 elems each; fp16 single into A tile (pitch 144)
    {
        const int tt = tid >> 2, sub = tid & 3;
        const size_t base = ((size_t)(t0 + tt)) * 64 + sub * 16;
        float v[16];
        const float4* ap = (const float4*)(g_attn + base);
        #pragma unroll
        for (int q = 0; q < 4; q++) {
            float4 f = ap[q];
            v[4*q+0] = f.x; v[4*q+1] = f.y; v[4*q+2] = f.z; v[4*q+3] = f.w;
        }
        float s = 0.f;
        #pragma unroll
        for (int q = 0; q < 16; q++) s += v[q];
        s += __shfl_xor_sync(0xffffffffu, s, 1);
        s += __shfl_xor_sync(0xffffffffu, s, 2);
        const float mean = s * (1.f / 64.f);
        float vs = 0.f;
        #pragma unroll
        for (int q = 0; q < 16; q++) { float d = v[q] - mean; vs += d * d; }
        vs += __shfl_xor_sync(0xffffffffu, vs, 1);
        vs += __shfl_xor_sync(0xffffffffu, vs, 2);
        const float rs = rsqrtf(vs * (1.f / 64.f) + 1e-5f);
        float r[16];
        #pragma unroll
        for (int q = 0; q < 16; q++) {
            const int d = sub * 16 + q;
            r[q] = (v[q] - mean) * rs * g2[d] + b2v[d];
        }
        uint32_t hw[8];
        #pragma unroll
        for (int q = 0; q < 8; q++) hw[q] = packh2(r[2*q], r[2*q+1]);
        char* dst = smc + F3_A + (tt * 144 + sub * 32);
        *(uint4*)(dst)      = make_uint4(hw[0], hw[1], hw[2], hw[3]);
        *(uint4*)(dst + 16) = make_uint4(hw[4], hw[5], hw[6], hw[7]);
    }
    CPW(0);
    __syncthreads();

    const int wid = tid >> 5, lane = tid & 31;
    const int g = lane >> 3, lr = lane & 7;
    const int tg = (wid & 3) * 16;     // token group 0..48
    const int cg = wid >> 2;           // col/k group 0..1
    const int n0 = cg * 128;

    const uint32_t aA  = sb + F3_A  + (uint32_t)(tg + (g & 1) * 8 + lr) * 144 + (g >> 1) * 16;
    const uint32_t bW1 = sb + F3_W1 + (uint32_t)(n0 + (g >> 1) * 8 + lr) * 272 + (g & 1) * 16;

    // ---- GEMM1: s[16][4] = A(fp16) @ W1[:, n0:n0+128] (fp16 2-term) ----
    float s[16][4];
    #pragma unroll
    for (int j = 0; j < 16; j++)
        #pragma unroll
        for (int e = 0; e < 4; e++) s[j][e] = 0.f;

    #pragma unroll
    for (int ks = 0; ks < 4; ks++) {
        uint32_t a0, a1, a2, a3;
        LDSM_X4(a0, a1, a2, a3, aA + ks * 32);
        #pragma unroll
        for (int j = 0; j < 8; j++) {
            uint32_t wh0, wh1, wh2, wh3, wl0, wl1, wl2, wl3;
            LDSM_X4(wh0, wh1, wh2, wh3, bW1 + j * (16 * 272) + ks * 32);
            LDSM_X4(wl0, wl1, wl2, wl3, bW1 + j * (16 * 272) + 128 + ks * 32);
            mma_fp(s[2*j],     a0, a1, a2, a3, wh0, wh1);
            mma_fp(s[2*j + 1], a0, a1, a2, a3, wh2, wh3);
            mma_fp(s[2*j],     a0, a1, a2, a3, wl0, wl1);
            mma_fp(s[2*j + 1], a0, a1, a2, a3, wl2, wl3);
        }
    }

    // ---- gelu + pack H fragments in registers (A-fragment layout) ----
    const int c0 = 2 * (lane & 3);
    uint32_t ph[8][4];
    #pragma unroll
    for (int gk = 0; gk < 8; gk++) {
        const int colA = n0 + gk * 16 + c0;
        const int colB = colA + 8;
        const float bA0 = b1m[colA], bA1 = b1m[colA + 1];
        const float bB0 = b1m[colB], bB1 = b1m[colB + 1];
        ph[gk][0] = packh2(gelu_f(s[2*gk][0] + bA0),     gelu_f(s[2*gk][1] + bA1));
        ph[gk][1] = packh2(gelu_f(s[2*gk][2] + bA0),     gelu_f(s[2*gk][3] + bA1));
        ph[gk][2] = packh2(gelu_f(s[2*gk + 1][0] + bB0), gelu_f(s[2*gk + 1][1] + bB1));
        ph[gk][3] = packh2(gelu_f(s[2*gk + 1][2] + bB0), gelu_f(s[2*gk + 1][3] + bB1));
    }

    // ---- GEMM2: o = H @ W2, partial over k in [n0, n0+128) (fp16 single) ----
    const uint32_t bW2 = sb + F3_W2 + (uint32_t)((g >> 1) * 8 + lr) * 528
                       + (g & 1) * 16 + (uint32_t)n0 * 2;
    float o[8][4];
    #pragma unroll
    for (int j = 0; j < 8; j++)
        #pragma unroll
        for (int e = 0; e < 4; e++) o[j][e] = 0.f;

    #pragma unroll
    for (int kk = 0; kk < 8; kk++) {
        const uint32_t p0 = ph[kk][0], p1 = ph[kk][1], p2 = ph[kk][2], p3 = ph[kk][3];
        #pragma unroll
        for (int j = 0; j < 4; j++) {
            uint32_t w0, w1, w2, w3;
            LDSM_X4(w0, w1, w2, w3, bW2 + j * (16 * 528) + kk * 32);
            mma_fp(o[2*j],     p0, p1, p2, p3, w0, w1);
            mma_fp(o[2*j + 1], p0, p1, p2, p3, w2, w3);
        }
    }

    // ---- 2-way K-split reduce via dead W1 region ----
    __syncthreads();   // all A/W1 reads complete

    const int rowL = tg + (lane >> 2);
    if (cg == 1) {
        float* rb = (float*)(smc + F3_W1);   // [64][68] floats
        #pragma unroll
        for (int idx = 0; idx < 8; idx++) {
            const int col = (idx >> 1) * 16 + (idx & 1) * 8 + c0;
            *(float2*)(rb + rowL * 68 + col)       = make_float2(o[idx][0], o[idx][1]);
            *(float2*)(rb + (rowL + 8) * 68 + col) = make_float2(o[idx][2], o[idx][3]);
        }
    }
    __syncthreads();

    if (cg == 0) {
        const float* rb = (const float*)(smc + F3_W1);
        const int r0 = t0 + rowL;
        #pragma unroll
        for (int idx = 0; idx < 8; idx++) {
            const int col = (idx >> 1) * 16 + (idx & 1) * 8 + c0;
            const float2 pa = *(const float2*)(rb + rowL * 68 + col);
            const float2 pb = *(const float2*)(rb + (rowL + 8) * 68 + col);
            const float bb0 = b2m[col], bb1 = b2m[col + 1];
            const size_t na = (size_t)r0 * 64 + col;
            const size_t nb = (size_t)(r0 + 8) * 64 + col;
            const float2 xa = *(const float2*)(x + na);
            const float2 xb = *(const float2*)(x + nb);
            *(float2*)(out + na) = make_float2(o[idx][0] + pa.x + bb0 + xa.x,
                                               o[idx][1] + pa.y + bb1 + xa.y);
            *(float2*)(out + nb) = make_float2(o[idx][2] + pb.x + bb0 + xb.x,
                                               o[idx][3] + pb.y + bb1 + xb.y);
        }
    }
}

// ===========================================================================
extern "C" void kernel_launch(void* const* d_in, const int* in_sizes, int n_in,
                              void* d_out, int out_size)
{
    const float* x    = (const float*)d_in[0];
    const float* ln1g = (const float*)d_in[1];
    const float* ln1b = (const float*)d_in[2];
    const float* Wp   = (const float*)d_in[3];
    const float* bp   = (const float*)d_in[4];
    const float* ln2g = (const float*)d_in[5];
    const float* ln2b = (const float*)d_in[6];
    const float* W1   = (const float*)d_in[7];
    const float* b1   = (const float*)d_in[8];
    const float* W2   = (const float*)d_in[9];
    const float* b2   = (const float*)d_in[10];
    float* out = (float*)d_out;

    cudaFuncSetAttribute(k1_ln_qkv,   cudaFuncAttributeMaxDynamicSharedMemorySize, K1_TOTAL);
    cudaFuncSetAttribute(k2_attn_mma, cudaFuncAttributeMaxDynamicSharedMemorySize, SM2_TOTAL);
    cudaFuncSetAttribute(k3_fused,    cudaFuncAttributeMaxDynamicSharedMemorySize, F3_TOTAL);

    kprep<<<64, 256>>>(Wp, W1, W2);
    k1_ln_qkv<<<NTOK / 64, 256, K1_TOTAL>>>(x, ln1g, ln1b, bp);
    k2_attn_mma<<<dim3(SS / 128, BB * HH), 256, SM2_TOTAL>>>();
    k3_fused<<<NTOK / 64, 256, F3_TOTAL>>>(ln2g, ln2b, b1, x, b2, out);
}

// round 13
// speedup vs baseline: 1.0911x; 1.0256x over previous
#include <cuda_runtime.h>
#include <cuda_bf16.h>
#include <cuda_fp16.h>
#include <math.h>
#include <stdint.h>

#define BB 4
#define SS 2048
#define HH 8
#define DD 64
#define NTOK (BB*SS*HH)   // 65536 tokens

// Scratch (allocation-free rule: __device__ globals)
__device__ __nv_bfloat16 g_qkh[(size_t)NTOK * 128];  // [n][128] q|k hi parts
__device__ __nv_bfloat16 g_qkl[(size_t)NTOK * 128];  // [n][128] q|k lo parts
__device__ __half        g_v  [(size_t)NTOK * 64];   // [n][64]  v fp16
__device__ float         g_attn[(size_t)NTOK * 64];  // [n][64]  attention out
// Pre-transposed / split weights
__device__ __nv_bfloat16 g_wph[192 * 64];            // Wp^T [n][k] hi (bf16)
__device__ __nv_bfloat16 g_wpl[192 * 64];            // Wp^T [n][k] lo (bf16)
__device__ __half        g_w1h[256 * 64];            // W1^T [n][k] (fp16 single)
__device__ __half        g_w2h[64 * 256];            // W2^T [n][k] (fp16)

// ===========================================================================
// helpers
// ===========================================================================
__device__ __forceinline__ uint32_t smem_u32(const void* p) {
    uint32_t a;
    asm("{ .reg .u64 t; cvta.to.shared.u64 t, %1; cvt.u32.u64 %0, t; }"
        : "=r"(a) : "l"(p));
    return a;
}
__device__ __forceinline__ uint32_t packh2(float a, float b) {
    __half2 h = __floats2half2_rn(a, b);
    return *reinterpret_cast<uint32_t*>(&h);
}
__device__ __forceinline__ uint32_t packbf2(float a, float b) {
    __nv_bfloat16 ha = __float2bfloat16(a), hb = __float2bfloat16(b);
    return (uint32_t)__bfloat16_as_ushort(ha) | ((uint32_t)__bfloat16_as_ushort(hb) << 16);
}
__device__ __forceinline__ void split2bf(float a, float b, uint32_t& hi, uint32_t& lo) {
    __nv_bfloat16 ha = __float2bfloat16(a), hb = __float2bfloat16(b);
    hi = (uint32_t)__bfloat16_as_ushort(ha) | ((uint32_t)__bfloat16_as_ushort(hb) << 16);
    lo = packbf2(a - __bfloat162float(ha), b - __bfloat162float(hb));
}
__device__ __forceinline__ float gelu_f(float z) {
    return 0.5f * z * (1.f + erff(z * 0.70710678118654752f));
}

#define LDSM_X4(r0,r1,r2,r3, addr) \
    asm volatile("ldmatrix.sync.aligned.m8n8.x4.shared.b16 {%0,%1,%2,%3}, [%4];" \
        : "=r"(r0), "=r"(r1), "=r"(r2), "=r"(r3) : "r"(addr))
#define LDSM_X4_T(r0,r1,r2,r3, addr) \
    asm volatile("ldmatrix.sync.aligned.m8n8.x4.trans.shared.b16 {%0,%1,%2,%3}, [%4];" \
        : "=r"(r0), "=r"(r1), "=r"(r2), "=r"(r3) : "r"(addr))

__device__ __forceinline__ void mma_bf(float* d, uint32_t a0, uint32_t a1,
                                       uint32_t a2, uint32_t a3,
                                       uint32_t b0, uint32_t b1) {
    asm volatile(
        "mma.sync.aligned.m16n8k16.row.col.f32.bf16.bf16.f32 "
        "{%0,%1,%2,%3}, {%4,%5,%6,%7}, {%8,%9}, {%0,%1,%2,%3};"
        : "+f"(d[0]), "+f"(d[1]), "+f"(d[2]), "+f"(d[3])
        : "r"(a0), "r"(a1), "r"(a2), "r"(a3), "r"(b0), "r"(b1));
}
__device__ __forceinline__ void mma_fp(float* d, uint32_t a0, uint32_t a1,
                                       uint32_t a2, uint32_t a3,
                                       uint32_t b0, uint32_t b1) {
    asm volatile(
        "mma.sync.aligned.m16n8k16.row.col.f32.f16.f16.f32 "
        "{%0,%1,%2,%3}, {%4,%5,%6,%7}, {%8,%9}, {%0,%1,%2,%3};"
        : "+f"(d[0]), "+f"(d[1]), "+f"(d[2]), "+f"(d[3])
        : "r"(a0), "r"(a1), "r"(a2), "r"(a3), "r"(b0), "r"(b1));
}

#define CPA(dst, src) asm volatile("cp.async.cg.shared.global [%0], [%1], 16;" \
        :: "r"(dst), "l"(src) : "memory")
#define CPC() asm volatile("cp.async.commit_group;" ::: "memory")
#define CPW(n) asm volatile("cp.async.wait_group %0;" :: "n"(n) : "memory")

// ===========================================================================
// Kernel 0: weight prep (transpose + split).  64 blocks x 256 threads.
// ===========================================================================
__global__ __launch_bounds__(256)
void kprep(const float* __restrict__ Wp, const float* __restrict__ W1,
           const float* __restrict__ W2)
{
    const int i = blockIdx.x * 256 + threadIdx.x;   // 0..16383
    if (i < 12288) {
        const int k = i / 192, n = i % 192;         // Wp [64][192]
        const float v = Wp[k * 192 + n];
        __nv_bfloat16 hv = __float2bfloat16(v);
        g_wph[n * 64 + k] = hv;
        g_wpl[n * 64 + k] = __float2bfloat16(v - __bfloat162float(hv));
    }
    {
        const int k = i >> 8, n = i & 255;          // W1 [64][256] -> fp16 single
        g_w1h[n * 64 + k] = __float2half(W1[k * 256 + n]);
    }
    {
        const int k = i >> 6, n = i & 63;           // W2 [256][64]
        g_w2h[n * 256 + k] = __float2half(W2[k * 64 + n]);
    }
}

// ===========================================================================
// Kernel 1: LN1 + QKV projection via HMMA (bf16 3-term).  (unchanged)
// ===========================================================================
#define K1_SW 17408
#define K1_TOTAL (K1_SW + 192 * 272)    // 69632

__global__ __launch_bounds__(256)
void k1_ln_qkv(const float* __restrict__ x,
               const float* __restrict__ g1, const float* __restrict__ b1v,
               const float* __restrict__ bp)
{
    extern __shared__ char smc[];
    const uint32_t sb = smem_u32(smc);
    const int tid = threadIdx.x;
    const int t0 = blockIdx.x * 64;

    for (int it = tid; it < 3072; it += 256) {
        const int n = it >> 4, c = it & 15;
        const char* src = (c < 8)
            ? (const char*)(g_wph + n * 64 + c * 8)
            : (const char*)(g_wpl + n * 64 + (c - 8) * 8);
        CPA(sb + K1_SW + n * 272 + c * 16, src);
    }
    CPC();

    {
        const int tt = tid >> 2, sub = tid & 3;
        const size_t base = ((size_t)(t0 + tt)) * 64 + sub * 16;
        float v[16];
        const float4* xp = (const float4*)(x + base);
        #pragma unroll
        for (int q = 0; q < 4; q++) {
            float4 f = xp[q];
            v[4*q+0] = f.x; v[4*q+1] = f.y; v[4*q+2] = f.z; v[4*q+3] = f.w;
        }
        float s = 0.f;
        #pragma unroll
        for (int q = 0; q < 16; q++) s += v[q];
        s += __shfl_xor_sync(0xffffffffu, s, 1);
        s += __shfl_xor_sync(0xffffffffu, s, 2);
        const float mean = s * (1.f / 64.f);
        float vs = 0.f;
        #pragma unroll
        for (int q = 0; q < 16; q++) { float d = v[q] - mean; vs += d * d; }
        vs += __shfl_xor_sync(0xffffffffu, vs, 1);
        vs += __shfl_xor_sync(0xffffffffu, vs, 2);
        const float rs = rsqrtf(vs * (1.f / 64.f) + 1e-5f);
        float r[16];
        #pragma unroll
        for (int q = 0; q < 16; q++) {
            const int d = sub * 16 + q;
            r[q] = (v[q] - mean) * rs * g1[d] + b1v[d];
        }
        uint32_t hw[8], lw[8];
        #pragma unroll
        for (int q = 0; q < 8; q++) split2bf(r[2*q], r[2*q+1], hw[q], lw[q]);
        char* dst = smc + (tt * 272 + sub * 32);
        *(uint4*)(dst)            = make_uint4(hw[0], hw[1], hw[2], hw[3]);
        *(uint4*)(dst + 16)       = make_uint4(hw[4], hw[5], hw[6], hw[7]);
        *(uint4*)(dst + 128)      = make_uint4(lw[0], lw[1], lw[2], lw[3]);
        *(uint4*)(dst + 128 + 16) = make_uint4(lw[4], lw[5], lw[6], lw[7]);
    }
    CPW(0);
    __syncthreads();

    const int wid = tid >> 5, lane = tid & 31;
    const int g = lane >> 3, lr = lane & 7;
    const int tg = (wid & 3) * 16;
    const int n0 = (wid >> 2) * 96;

    const uint32_t aA = sb + (uint32_t)(tg + (g & 1) * 8 + lr) * 272 + (g >> 1) * 16;
    const uint32_t bW = sb + K1_SW + (uint32_t)(n0 + (g >> 1) * 8 + lr) * 272 + (g & 1) * 16;

    float s[12][4];
    #pragma unroll
    for (int j = 0; j < 12; j++)
        #pragma unroll
        for (int e = 0; e < 4; e++) s[j][e] = 0.f;

    #pragma unroll
    for (int ks = 0; ks < 4; ks++) {
        uint32_t ah0, ah1, ah2, ah3, al0, al1, al2, al3;
        LDSM_X4(ah0, ah1, ah2, ah3, aA + ks * 32);
        LDSM_X4(al0, al1, al2, al3, aA + 128 + ks * 32);
        #pragma unroll
        for (int j = 0; j < 6; j++) {
            uint32_t wh0, wh1, wh2, wh3, wl0, wl1, wl2, wl3;
            LDSM_X4(wh0, wh1, wh2, wh3, bW + j * (16 * 272) + ks * 32);
            LDSM_X4(wl0, wl1, wl2, wl3, bW + j * (16 * 272) + 128 + ks * 32);
            mma_bf(s[2*j],     ah0, ah1, ah2, ah3, wh0, wh1);
            mma_bf(s[2*j + 1], ah0, ah1, ah2, ah3, wh2, wh3);
            mma_bf(s[2*j],     al0, al1, al2, al3, wh0, wh1);
            mma_bf(s[2*j + 1], al0, al1, al2, al3, wh2, wh3);
            mma_bf(s[2*j],     ah0, ah1, ah2, ah3, wl0, wl1);
            mma_bf(s[2*j + 1], ah0, ah1, ah2, ah3, wl2, wl3);
        }
    }

    const int r0 = t0 + tg + (lane >> 2);
    const int c0 = 2 * (lane & 3);
    #pragma unroll
    for (int idx = 0; idx < 12; idx++) {
        const int col = n0 + (idx >> 1) * 16 + (idx & 1) * 8 + c0;
        const float bb0 = bp[col], bb1 = bp[col + 1];
        const float v0 = s[idx][0] + bb0, v1 = s[idx][1] + bb1;
        const float v2 = s[idx][2] + bb0, v3 = s[idx][3] + bb1;
        if (col < 128) {
            uint32_t h01, l01, h23, l23;
            split2bf(v0, v1, h01, l01);
            split2bf(v2, v3, h23, l23);
            *(uint32_t*)(g_qkh + (size_t)r0 * 128 + col)       = h01;
            *(uint32_t*)(g_qkl + (size_t)r0 * 128 + col)       = l01;
            *(uint32_t*)(g_qkh + (size_t)(r0 + 8) * 128 + col) = h23;
            *(uint32_t*)(g_qkl + (size_t)(r0 + 8) * 128 + col) = l23;
        } else {
            *(uint32_t*)(g_v + (size_t)r0 * 64 + col - 128)       = packh2(v0, v1);
            *(uint32_t*)(g_v + (size_t)(r0 + 8) * 64 + col - 128) = packh2(v2, v3);
        }
    }
}

// smem byte layout for k2 (unchanged)
#define QPITCH 272
#define KPITCH 272
#define VPITCH 144
#define SM_Q   0
#define SM_KB  (128 * QPITCH)               // 34816
#define KBUF   (64 * KPITCH)                // 17408
#define SM_VB  (SM_KB + 2 * KBUF)           // 69632
#define VBUF   (64 * VPITCH)                // 9216
#define SM2_TOTAL (SM_VB + 2 * VBUF)        // 88064

// ===========================================================================
// Kernel 2: flash attention.  (unchanged — known-good)
// ===========================================================================
__global__ __launch_bounds__(256, 2)
void k2_attn_mma()
{
    extern __shared__ char smc[];
    const uint32_t sb = smem_u32(smc);

    const int tid  = threadIdx.x;
    const int wid  = tid >> 5;
    const int lane = tid & 31;
    const int b = blockIdx.y >> 3, h = blockIdx.y & 7;
    const int q0 = blockIdx.x * 128;
    const int m0 = wid * 16;

    const int g  = lane >> 3;
    const int lr = lane & 7;

    const uint32_t aQ   = sb + SM_Q + (uint32_t)(m0 + (g & 1) * 8 + lr) * QPITCH + (g >> 1) * 16;
    const uint32_t kOff = (uint32_t)((g >> 1) * 8 + lr) * KPITCH + (g & 1) * 16;
    const uint32_t vOff = (uint32_t)((g & 1) * 8 + lr) * VPITCH + (g >> 1) * 16;

    {
        for (int it = tid; it < 2048; it += 256) {
            const int row = it >> 4, c = it & 15;
            const size_t n = ((size_t)(b * SS + q0 + row)) * HH + h;
            const char* src = (c < 8)
                ? (const char*)(g_qkh + n * 128 + c * 8)
                : (const char*)(g_qkl + n * 128 + (c - 8) * 8);
            CPA(sb + SM_Q + row * QPITCH + c * 16, src);
        }
        for (int it = tid; it < 1024; it += 256) {
            const int row = it >> 4, c = it & 15;
            const size_t n = ((size_t)(b * SS + row)) * HH + h;
            const char* src = (c < 8)
                ? (const char*)(g_qkh + n * 128 + 64 + c * 8)
                : (const char*)(g_qkl + n * 128 + 64 + (c - 8) * 8);
            CPA(sb + SM_KB + row * KPITCH + c * 16, src);
        }
        for (int it = tid; it < 512; it += 256) {
            const int row = it >> 3, c = it & 7;
            const size_t n = ((size_t)(b * SS + row)) * HH + h;
            CPA(sb + SM_VB + row * VPITCH + c * 16, (const char*)(g_v + n * 64 + c * 8));
        }
        CPC();
    }

    float o[8][4];
    #pragma unroll
    for (int j = 0; j < 8; j++)
        #pragma unroll
        for (int e = 0; e < 4; e++) o[j][e] = 0.f;
    float mrow0 = -INFINITY, mrow1 = -INFINITY;
    float lsum0 = 0.f, lsum1 = 0.f;

    for (int kt = 0; kt < SS / 64; kt++) {
        __syncthreads();
        if (kt + 1 < SS / 64) {
            const int k0n = (kt + 1) * 64;
            const uint32_t dK = sb + SM_KB + ((kt + 1) & 1) * KBUF;
            const uint32_t dV = sb + SM_VB + ((kt + 1) & 1) * VBUF;
            for (int it = tid; it < 1024; it += 256) {
                const int row = it >> 4, c = it & 15;
                const size_t n = ((size_t)(b * SS + k0n + row)) * HH + h;
                const char* src = (c < 8)
                    ? (const char*)(g_qkh + n * 128 + 64 + c * 8)
                    : (const char*)(g_qkl + n * 128 + 64 + (c - 8) * 8);
                CPA(dK + row * KPITCH + c * 16, src);
            }
            for (int it = tid; it < 512; it += 256) {
                const int row = it >> 3, c = it & 7;
                const size_t n = ((size_t)(b * SS + k0n + row)) * HH + h;
                CPA(dV + row * VPITCH + c * 16, (const char*)(g_v + n * 64 + c * 8));
            }
            CPC();
            CPW(1);
        } else {
            CPW(0);
        }
        __syncthreads();

        const uint32_t bK = sb + SM_KB + (kt & 1) * KBUF + kOff;
        const uint32_t bV = sb + SM_VB + (kt & 1) * VBUF + vOff;

        float s[8][4];
        #pragma unroll
        for (int j = 0; j < 8; j++)
            #pragma unroll
            for (int e = 0; e < 4; e++) s[j][e] = 0.f;

        #pragma unroll
        for (int ks = 0; ks < 4; ks++) {
            uint32_t qh0, qh1, qh2, qh3, ql0, ql1, ql2, ql3;
            LDSM_X4(qh0, qh1, qh2, qh3, aQ + ks * 32);
            LDSM_X4(ql0, ql1, ql2, ql3, aQ + 128 + ks * 32);
            #pragma unroll
            for (int j = 0; j < 4; j++) {
                uint32_t kh0, kh1, kh2, kh3, kl0, kl1, kl2, kl3;
                LDSM_X4(kh0, kh1, kh2, kh3, bK + j * (16 * KPITCH) + ks * 32);
                LDSM_X4(kl0, kl1, kl2, kl3, bK + j * (16 * KPITCH) + 128 + ks * 32);
                mma_bf(s[2*j],     qh0, qh1, qh2, qh3, kh0, kh1);
                mma_bf(s[2*j + 1], qh0, qh1, qh2, qh3, kh2, kh3);
                mma_bf(s[2*j],     ql0, ql1, ql2, ql3, kh0, kh1);
                mma_bf(s[2*j + 1], ql0, ql1, ql2, ql3, kh2, kh3);
                mma_bf(s[2*j],     qh0, qh1, qh2, qh3, kl0, kl1);
                mma_bf(s[2*j + 1], qh0, qh1, qh2, qh3, kl2, kl3);
            }
        }

        float t0 = -INFINITY, t1 = -INFINITY;
        #pragma unroll
        for (int j = 0; j < 8; j++) {
            t0 = fmaxf(t0, fmaxf(s[j][0], s[j][1]));
            t1 = fmaxf(t1, fmaxf(s[j][2], s[j][3]));
        }
        t0 = fmaxf(t0, __shfl_xor_sync(0xffffffffu, t0, 1));
        t0 = fmaxf(t0, __shfl_xor_sync(0xffffffffu, t0, 2));
        t1 = fmaxf(t1, __shfl_xor_sync(0xffffffffu, t1, 1));
        t1 = fmaxf(t1, __shfl_xor_sync(0xffffffffu, t1, 2));
        const float mn0 = fmaxf(mrow0, t0);
        const float mn1 = fmaxf(mrow1, t1);
        const float sc0 = __expf(mrow0 - mn0);
        const float sc1 = __expf(mrow1 - mn1);
        mrow0 = mn0; mrow1 = mn1;

        float acc0 = 0.f, acc1 = 0.f;
        #pragma unroll
        for (int j = 0; j < 8; j++) {
            s[j][0] = __expf(s[j][0] - mn0);
            s[j][1] = __expf(s[j][1] - mn0);
            s[j][2] = __expf(s[j][2] - mn1);
            s[j][3] = __expf(s[j][3] - mn1);
            acc0 += s[j][0] + s[j][1];
            acc1 += s[j][2] + s[j][3];
        }
        lsum0 = lsum0 * sc0 + acc0;
        lsum1 = lsum1 * sc1 + acc1;
        #pragma unroll
        for (int j = 0; j < 8; j++) {
            o[j][0] *= sc0; o[j][1] *= sc0;
            o[j][2] *= sc1; o[j][3] *= sc1;
        }

        #pragma unroll
        for (int kk = 0; kk < 4; kk++) {
            const uint32_t p0 = packh2(s[2*kk][0],     s[2*kk][1]);
            const uint32_t p1 = packh2(s[2*kk][2],     s[2*kk][3]);
            const uint32_t p2 = packh2(s[2*kk + 1][0], s[2*kk + 1][1]);
            const uint32_t p3 = packh2(s[2*kk + 1][2], s[2*kk + 1][3]);
            #pragma unroll
            for (int j = 0; j < 4; j++) {
                uint32_t v0, v1, v2, v3;
                LDSM_X4_T(v0, v1, v2, v3, bV + kk * (16 * VPITCH) + j * 32);
                mma_fp(o[2*j],     p0, p1, p2, p3, v0, v1);
                mma_fp(o[2*j + 1], p0, p1, p2, p3, v2, v3);
            }
        }
    }

    lsum0 += __shfl_xor_sync(0xffffffffu, lsum0, 1);
    lsum0 += __shfl_xor_sync(0xffffffffu, lsum0, 2);
    lsum1 += __shfl_xor_sync(0xffffffffu, lsum1, 1);
    lsum1 += __shfl_xor_sync(0xffffffffu, lsum1, 2);
    const float inv0 = 1.f / lsum0, inv1 = 1.f / lsum1;

    const int r0 = q0 + m0 + (lane >> 2);
    const int c0 = (lane & 3) * 2;
    const size_t n0 = ((size_t)(b * SS + r0)) * HH + h;
    const size_t n1 = ((size_t)(b * SS + r0 + 8)) * HH + h;
    #pragma unroll
    for (int j = 0; j < 8; j++) {
        float2 v0 = make_float2(o[j][0] * inv0, o[j][1] * inv0);
        float2 v1 = make_float2(o[j][2] * inv1, o[j][3] * inv1);
        *(float2*)(g_attn + n0 * 64 + 8 * j + c0) = v0;
        *(float2*)(g_attn + n1 * 64 + 8 * j + c0) = v1;
    }
}

// ===========================================================================
// Kernel 3 (fused v3): LN2 + GEMM1 (A fp16 x W1 fp16 SINGLE-term) + gelu
// + GEMM2 (fp16 single, 2-way K-split) + reduce via dead W1 region
// + bias + residual -> out.
// 64 tokens/block, 256 threads (8 warps), 2 CTAs/SM.  grid = NTOK/64 = 1024.
// warp w: tokens (w&3)*16.., col/k-range (w>>2)*128.
// smem: A @0 (9216, pitch 144) ; W1 @9216 (36864, pitch 144, reused as reduce) ;
//       W2h @46080 (33792, pitch 528).  Total 79872.
// ===========================================================================
#define F3_A   0
#define F3_W1  9216
#define F3_W2  46080
#define F3_TOTAL 79872

__global__ __launch_bounds__(256, 2)
void k3_fused(const float* __restrict__ g2, const float* __restrict__ b2v,
              const float* __restrict__ b1m,
              const float* __restrict__ x, const float* __restrict__ b2m,
              float* __restrict__ out)
{
    extern __shared__ char smc[];
    const uint32_t sb = smem_u32(smc);
    const int tid = threadIdx.x;
    const int t0 = blockIdx.x * 64;

    // async-load W1 fp16 single: 256 rows x 8 chunks, pitch 144
    for (int it = tid; it < 2048; it += 256) {
        const int n = it >> 3, c = it & 7;
        CPA(sb + F3_W1 + n * 144 + c * 16, (const char*)(g_w1h + n * 64 + c * 8));
    }
    // async-load W2h fp16: 64 rows x 32 chunks, pitch 528
    for (int it = tid; it < 2048; it += 256) {
        const int n = it >> 5, c = it & 31;
        CPA(sb + F3_W2 + n * 528 + c * 16, (const char*)(g_w2h + n * 256 + c * 8));
    }
    CPC();

    // LN2: 4 threads/token, 16 elems each; fp16 single into A tile (pitch 144)
    {
        const int tt = tid >> 2, sub = tid & 3;
        const size_t base = ((size_t)(t0 + tt)) * 64 + sub * 16;
        float v[16];
        const float4* ap = (const float4*)(g_attn + base);
        #pragma unroll
        for (int q = 0; q < 4; q++) {
            float4 f = ap[q];
            v[4*q+0] = f.x; v[4*q+1] = f.y; v[4*q+2] = f.z; v[4*q+3] = f.w;
        }
        float s = 0.f;
        #pragma unroll
        for (int q = 0; q < 16; q++) s += v[q];
        s += __shfl_xor_sync(0xffffffffu, s, 1);
        s += __shfl_xor_sync(0xffffffffu, s, 2);
        const float mean = s * (1.f / 64.f);
        float vs = 0.f;
        #pragma unroll
        for (int q = 0; q < 16; q++) { float d = v[q] - mean; vs += d * d; }
        vs += __shfl_xor_sync(0xffffffffu, vs, 1);
        vs += __shfl_xor_sync(0xffffffffu, vs, 2);
        const float rs = rsqrtf(vs * (1.f / 64.f) + 1e-5f);
        float r[16];
        #pragma unroll
        for (int q = 0; q < 16; q++) {
            const int d = sub * 16 + q;
            r[q] = (v[q] - mean) * rs * g2[d] + b2v[d];
        }
        uint32_t hw[8];
        #pragma unroll
        for (int q = 0; q < 8; q++) hw[q] = packh2(r[2*q], r[2*q+1]);
        char* dst = smc + F3_A + (tt * 144 + sub * 32);
        *(uint4*)(dst)      = make_uint4(hw[0], hw[1], hw[2], hw[3]);
        *(uint4*)(dst + 16) = make_uint4(hw[4], hw[5], hw[6], hw[7]);
    }
    CPW(0);
    __syncthreads();

    const int wid = tid >> 5, lane = tid & 31;
    const int g = lane >> 3, lr = lane & 7;
    const int tg = (wid & 3) * 16;     // token group 0..48
    const int cg = wid >> 2;           // col/k group 0..1
    const int n0 = cg * 128;

    const uint32_t aA  = sb + F3_A  + (uint32_t)(tg + (g & 1) * 8 + lr) * 144 + (g >> 1) * 16;
    const uint32_t bW1 = sb + F3_W1 + (uint32_t)(n0 + (g >> 1) * 8 + lr) * 144 + (g & 1) * 16;

    // ---- GEMM1: s[16][4] = A(fp16) @ W1[:, n0:n0+128] (fp16 single) ----
    float s[16][4];
    #pragma unroll
    for (int j = 0; j < 16; j++)
        #pragma unroll
        for (int e = 0; e < 4; e++) s[j][e] = 0.f;

    #pragma unroll
    for (int ks = 0; ks < 4; ks++) {
        uint32_t a0, a1, a2, a3;
        LDSM_X4(a0, a1, a2, a3, aA + ks * 32);
        #pragma unroll
        for (int j = 0; j < 8; j++) {
            uint32_t w0, w1, w2, w3;
            LDSM_X4(w0, w1, w2, w3, bW1 + j * (16 * 144) + ks * 32);
            mma_fp(s[2*j],     a0, a1, a2, a3, w0, w1);
            mma_fp(s[2*j + 1], a0, a1, a2, a3, w2, w3);
        }
    }

    // ---- gelu + pack H fragments in registers (A-fragment layout) ----
    const int c0 = 2 * (lane & 3);
    uint32_t ph[8][4];
    #pragma unroll
    for (int gk = 0; gk < 8; gk++) {
        const int colA = n0 + gk * 16 + c0;
        const int colB = colA + 8;
        const float bA0 = b1m[colA], bA1 = b1m[colA + 1];
        const float bB0 = b1m[colB], bB1 = b1m[colB + 1];
        ph[gk][0] = packh2(gelu_f(s[2*gk][0] + bA0),     gelu_f(s[2*gk][1] + bA1));
        ph[gk][1] = packh2(gelu_f(s[2*gk][2] + bA0),     gelu_f(s[2*gk][3] + bA1));
        ph[gk][2] = packh2(gelu_f(s[2*gk + 1][0] + bB0), gelu_f(s[2*gk + 1][1] + bB1));
        ph[gk][3] = packh2(gelu_f(s[2*gk + 1][2] + bB0), gelu_f(s[2*gk + 1][3] + bB1));
    }

    // ---- GEMM2: o = H @ W2, partial over k in [n0, n0+128) (fp16 single) ----
    const uint32_t bW2 = sb + F3_W2 + (uint32_t)((g >> 1) * 8 + lr) * 528
                       + (g & 1) * 16 + (uint32_t)n0 * 2;
    float o[8][4];
    #pragma unroll
    for (int j = 0; j < 8; j++)
        #pragma unroll
        for (int e = 0; e < 4; e++) o[j][e] = 0.f;

    #pragma unroll
    for (int kk = 0; kk < 8; kk++) {
        const uint32_t p0 = ph[kk][0], p1 = ph[kk][1], p2 = ph[kk][2], p3 = ph[kk][3];
        #pragma unroll
        for (int j = 0; j < 4; j++) {
            uint32_t w0, w1, w2, w3;
            LDSM_X4(w0, w1, w2, w3, bW2 + j * (16 * 528) + kk * 32);
            mma_fp(o[2*j],     p0, p1, p2, p3, w0, w1);
            mma_fp(o[2*j + 1], p0, p1, p2, p3, w2, w3);
        }
    }

    // ---- 2-way K-split reduce via dead W1 region ----
    __syncthreads();   // all A/W1 reads complete

    const int rowL = tg + (lane >> 2);
    if (cg == 1) {
        float* rb = (float*)(smc + F3_W1);   // [64][68] floats = 17408B < 36864B
        #pragma unroll
        for (int idx = 0; idx < 8; idx++) {
            const int col = (idx >> 1) * 16 + (idx & 1) * 8 + c0;
            *(float2*)(rb + rowL * 68 + col)       = make_float2(o[idx][0], o[idx][1]);
            *(float2*)(rb + (rowL + 8) * 68 + col) = make_float2(o[idx][2], o[idx][3]);
        }
    }
    __syncthreads();

    if (cg == 0) {
        const float* rb = (const float*)(smc + F3_W1);
        const int r0 = t0 + rowL;
        #pragma unroll
        for (int idx = 0; idx < 8; idx++) {
            const int col = (idx >> 1) * 16 + (idx & 1) * 8 + c0;
            const float2 pa = *(const float2*)(rb + rowL * 68 + col);
            const float2 pb = *(const float2*)(rb + (rowL + 8) * 68 + col);
            const float bb0 = b2m[col], bb1 = b2m[col + 1];
            const size_t na = (size_t)r0 * 64 + col;
            const size_t nb = (size_t)(r0 + 8) * 64 + col;
            const float2 xa = *(const float2*)(x + na);
            const float2 xb = *(const float2*)(x + nb);
            *(float2*)(out + na) = make_float2(o[idx][0] + pa.x + bb0 + xa.x,
                                               o[idx][1] + pa.y + bb1 + xa.y);
            *(float2*)(out + nb) = make_float2(o[idx][2] + pb.x + bb0 + xb.x,
                                               o[idx][3] + pb.y + bb1 + xb.y);
        }
    }
}

// ===========================================================================
extern "C" void kernel_launch(void* const* d_in, const int* in_sizes, int n_in,
                              void* d_out, int out_size)
{
    const float* x    = (const float*)d_in[0];
    const float* ln1g = (const float*)d_in[1];
    const float* ln1b = (const float*)d_in[2];
    const float* Wp   = (const float*)d_in[3];
    const float* bp   = (const float*)d_in[4];
    const float* ln2g = (const float*)d_in[5];
    const float* ln2b = (const float*)d_in[6];
    const float* W1   = (const float*)d_in[7];
    const float* b1   = (const float*)d_in[8];
    const float* W2   = (const float*)d_in[9];
    const float* b2   = (const float*)d_in[10];
    float* out = (float*)d_out;

    cudaFuncSetAttribute(k1_ln_qkv,   cudaFuncAttributeMaxDynamicSharedMemorySize, K1_TOTAL);
    cudaFuncSetAttribute(k2_attn_mma, cudaFuncAttributeMaxDynamicSharedMemorySize, SM2_TOTAL);
    cudaFuncSetAttribute(k3_fused,    cudaFuncAttributeMaxDynamicSharedMemorySize, F3_TOTAL);

    kprep<<<64, 256>>>(Wp, W1, W2);
    k1_ln_qkv<<<NTOK / 64, 256, K1_TOTAL>>>(x, ln1g, ln1b, bp);
    k2_attn_mma<<<dim3(SS / 128, BB * HH), 256, SM2_TOTAL>>>();
    k3_fused<<<NTOK / 64, 256, F3_TOTAL>>>(ln2g, ln2b, b1, x, b2, out);
}